// round 10
// baseline (speedup 1.0000x reference)
#include <cuda_runtime.h>
#include <cuda_bf16.h>
#include <cuda_fp16.h>
#include <cstdint>
#include <math.h>

// Problem dims
#define BATCH 4
#define NTOK  4096
#define NTOT  16384
#define C     256
#define FQ    32

// Scratch (device globals; allocation-free)
__device__ __nv_bfloat16 g_xh[NTOT * C];
__device__ __nv_bfloat16 g_xl[NTOT * C];
__device__ __nv_bfloat16 g_wqkh[C * 64];
__device__ __nv_bfloat16 g_wqkl[C * 64];
__device__ __nv_bfloat16 g_wvh[C * C];
__device__ __nv_bfloat16 g_wvl[C * C];
__device__ __nv_bfloat16 g_woh[C * C];
__device__ __nv_bfloat16 g_wol[C * C];
__device__ __nv_bfloat16 g_qh[NTOT * FQ];
__device__ __nv_bfloat16 g_ql[NTOT * FQ];
__device__ __nv_bfloat16 g_kh[NTOT * FQ];
__device__ __nv_bfloat16 g_kl[NTOT * FQ];
__device__ __half        g_vf[NTOT * C];   // V as single fp16
__device__ __nv_bfloat16 g_ah[NTOT * C];   // attended hi
__device__ __nv_bfloat16 g_al[NTOT * C];   // attended lo

// ---------------------------------------------------------------------------
// Helpers
// ---------------------------------------------------------------------------
__device__ __forceinline__ uint32_t smem_u32(const void* p) {
    uint32_t a;
    asm("{ .reg .u64 t; cvta.to.shared.u64 t, %1; cvt.u32.u64 %0, t; }"
        : "=r"(a) : "l"(p));
    return a;
}

#define CP_ASYNC16(dst, src) \
    asm volatile("cp.async.cg.shared.global [%0], [%1], 16;" \
                 :: "r"(dst), "l"(src))
#define CP_COMMIT() asm volatile("cp.async.commit_group;" ::: "memory")
#define CP_WAIT(n)  asm volatile("cp.async.wait_group %0;" :: "n"(n) : "memory")

#define LDSM_X4(r, a) \
    asm volatile("ldmatrix.sync.aligned.m8n8.x4.shared.b16 {%0,%1,%2,%3}, [%4];" \
                 : "=r"((r)[0]), "=r"((r)[1]), "=r"((r)[2]), "=r"((r)[3]) : "r"(a))
#define LDSM_X4T(r, a) \
    asm volatile("ldmatrix.sync.aligned.m8n8.x4.trans.shared.b16 {%0,%1,%2,%3}, [%4];" \
                 : "=r"((r)[0]), "=r"((r)[1]), "=r"((r)[2]), "=r"((r)[3]) : "r"(a))

#define MMA16816(d, a, b0, b1) \
    asm volatile("mma.sync.aligned.m16n8k16.row.col.f32.bf16.bf16.f32 " \
                 "{%0,%1,%2,%3}, {%4,%5,%6,%7}, {%8,%9}, {%0,%1,%2,%3};" \
                 : "+f"((d)[0]), "+f"((d)[1]), "+f"((d)[2]), "+f"((d)[3]) \
                 : "r"((a)[0]), "r"((a)[1]), "r"((a)[2]), "r"((a)[3]), \
                   "r"(b0), "r"(b1))

#define MMAF16(d, a, b0, b1) \
    asm volatile("mma.sync.aligned.m16n8k16.row.col.f32.f16.f16.f32 " \
                 "{%0,%1,%2,%3}, {%4,%5,%6,%7}, {%8,%9}, {%0,%1,%2,%3};" \
                 : "+f"((d)[0]), "+f"((d)[1]), "+f"((d)[2]), "+f"((d)[3]) \
                 : "r"((a)[0]), "r"((a)[1]), "r"((a)[2]), "r"((a)[3]), \
                   "r"(b0), "r"(b1))

__device__ __forceinline__ void split2(float a, float b,
                                       uint32_t& hp, uint32_t& lp) {
    __nv_bfloat16 ha = __float2bfloat16(a);
    __nv_bfloat16 hb = __float2bfloat16(b);
    float la = a - __bfloat162float(ha);
    float lb = b - __bfloat162float(hb);
    __nv_bfloat162 hh; hh.x = ha; hh.y = hb;
    __nv_bfloat162 ll;
    ll.x = __float2bfloat16(la); ll.y = __float2bfloat16(lb);
    hp = *(uint32_t*)&hh;
    lp = *(uint32_t*)&ll;
}

// exp(x) on the FMA pipe (no MUFU): 2^(x*log2e), deg-5 poly, exponent add.
// Valid for x in [-126, 0]; rel err ~2.4e-6.
__device__ __forceinline__ float fexp(float x) {
    const float L2E = 1.4426950408889634f;
    float y = x * L2E;
    float t = y + 12582912.0f;                 // round-to-nearest via magic
    int   n = __float_as_int(t) - 0x4B400000;  // n = round(y)
    float f = y - (t - 12582912.0f);           // f in [-0.5, 0.5]
    float q = 1.3333558146e-3f;
    q = fmaf(q, f, 9.6181291076e-3f);
    q = fmaf(q, f, 5.5504108664e-2f);
    q = fmaf(q, f, 2.4022650696e-1f);
    q = fmaf(q, f, 6.9314718056e-1f);
    q = fmaf(q, f, 1.0f);
    return __int_as_float(__float_as_int(q) + (n << 23));
}

// ---------------------------------------------------------------------------
// Split kernels (fp32 -> bf16 hi/lo)
// ---------------------------------------------------------------------------
__global__ void __launch_bounds__(256) split_kernel(
    const float* __restrict__ src, __nv_bfloat16* __restrict__ h,
    __nv_bfloat16* __restrict__ l, int n2)
{
    int i = blockIdx.x * 256 + threadIdx.x;
    if (i < n2) {
        float2 v = ((const float2*)src)[i];
        uint32_t hp, lp;
        split2(v.x, v.y, hp, lp);
        ((uint32_t*)h)[i] = hp;
        ((uint32_t*)l)[i] = lp;
    }
}

__global__ void __launch_bounds__(256) split_weights_kernel(
    const float* __restrict__ Wv, const float* __restrict__ Wo,
    const float* __restrict__ Wq, const float* __restrict__ Wk)
{
    int i2 = blockIdx.x * 256 + threadIdx.x;     // pair index
    if (i2 < 32768) {
        float2 v = ((const float2*)Wv)[i2];
        uint32_t hp, lp; split2(v.x, v.y, hp, lp);
        ((uint32_t*)g_wvh)[i2] = hp;
        ((uint32_t*)g_wvl)[i2] = lp;
    } else if (i2 < 65536) {
        int j = i2 - 32768;
        float2 v = ((const float2*)Wo)[j];
        uint32_t hp, lp; split2(v.x, v.y, hp, lp);
        ((uint32_t*)g_woh)[j] = hp;
        ((uint32_t*)g_wol)[j] = lp;
    } else if (i2 < 73728) {
        int j = i2 - 65536;
        int row = j >> 5;
        int col = (2 * j) & 63;
        float v0, v1;
        if (col < 32) { v0 = Wq[row * 32 + col];      v1 = Wq[row * 32 + col + 1]; }
        else          { v0 = Wk[row * 32 + col - 32]; v1 = Wk[row * 32 + col - 31]; }
        uint32_t hp, lp; split2(v0, v1, hp, lp);
        *(uint32_t*)&g_wqkh[row * 64 + col] = hp;
        *(uint32_t*)&g_wqkl[row * 64 + col] = lp;
    }
}

// ---------------------------------------------------------------------------
// bf16 mma GEMM body: out[rows m0..m0+127, N] = epi(A @ B), 3-term hi/lo.
// EPI: 0 = QK, 1 = V -> fp16, 2 = O -> fp32 + resid
// ---------------------------------------------------------------------------
#define ASWZ(row, c) ((uint32_t)((row) * 64 + ((((c) ^ (((row) >> 1) & 3))) << 4)))

template <int NTILE, int EPI>
__device__ __forceinline__ void gemm_body(
    const __nv_bfloat16* __restrict__ Ah, const __nv_bfloat16* __restrict__ Al,
    const __nv_bfloat16* __restrict__ Bh, const __nv_bfloat16* __restrict__ Bl,
    const float* __restrict__ bias, const float* __restrict__ bias2,
    const float* __restrict__ resid, float* __restrict__ out,
    int m0, int n0, char* smem)
{
    constexpr int NFULL = (EPI == 0) ? 64 : 256;
    constexpr int WNW = NTILE / 32;           // n-warps
    constexpr int WMW = 8 / WNW;              // m-warps
    constexpr int MF  = (128 / WMW) / 16;     // m-frags per warp
    constexpr int BROWB = NTILE * 2;          // B row bytes
    constexpr uint32_t OFF_B = 16384;
    constexpr uint32_t STAGE = OFF_B + 2 * (uint32_t)BROWB * 32;

    const uint32_t sb = smem_u32(smem);
    const int tid  = threadIdx.x;
    const int lane = tid & 31;
    const int w    = tid >> 5;
    const int wm0  = (w / WNW) * (128 / WMW);
    const int wn0  = (w % WNW) * 32;

    auto issue = [&](int s, int kt) {
        const uint32_t st = sb + (uint32_t)s * STAGE;
        #pragma unroll
        for (int i = 0; i < 2; i++) {
            int idx = tid + 256 * i;
            int row = idx >> 2, c = idx & 3;
            uint32_t so = ASWZ(row, c);
            const size_t ga = (size_t)(m0 + row) * 256 + kt * 32 + c * 8;
            CP_ASYNC16(st + so,        Ah + ga);
            CP_ASYNC16(st + 8192 + so, Al + ga);
        }
        if (NTILE == 128) {
            #pragma unroll
            for (int i = 0; i < 2; i++) {
                int idx = tid + 256 * i;
                int row = idx >> 4, c = idx & 15;
                uint32_t so = (uint32_t)(row * 256 +
                    ((((c & 8) | ((c ^ (row & 7)) & 7))) << 4));
                const size_t gb = (size_t)(kt * 32 + row) * NFULL + n0 + c * 8;
                CP_ASYNC16(st + OFF_B + so,              Bh + gb);
                CP_ASYNC16(st + OFF_B + BROWB * 32 + so, Bl + gb);
            }
        } else {
            int row = tid >> 3, c = tid & 7;
            uint32_t so = (uint32_t)(row * 128 + (((c ^ (row & 7))) << 4));
            const size_t gb = (size_t)(kt * 32 + row) * NFULL + n0 + c * 8;
            CP_ASYNC16(st + OFF_B + so,              Bh + gb);
            CP_ASYNC16(st + OFF_B + BROWB * 32 + so, Bl + gb);
        }
        CP_COMMIT();
    };

    float acc[MF][4][4];
    #pragma unroll
    for (int mf = 0; mf < MF; mf++)
        #pragma unroll
        for (int nf = 0; nf < 4; nf++)
            #pragma unroll
            for (int e = 0; e < 4; e++) acc[mf][nf][e] = 0.0f;

    issue(0, 0);

    #pragma unroll 1
    for (int kt = 0; kt < 8; kt++) {
        if (kt + 1 < 8) { issue((kt + 1) & 1, kt + 1); CP_WAIT(1); }
        else            { CP_WAIT(0); }
        __syncthreads();

        const uint32_t st = sb + (uint32_t)(kt & 1) * STAGE;

        #pragma unroll
        for (int kf = 0; kf < 2; kf++) {
            uint32_t afh[MF][4], afl[MF][4];
            #pragma unroll
            for (int mf = 0; mf < MF; mf++) {
                int row = wm0 + mf * 16 + (lane & 15);
                int c   = kf * 2 + (lane >> 4);
                uint32_t a = st + ASWZ(row, c);
                LDSM_X4(afh[mf], a);
                LDSM_X4(afl[mf], a + 8192);
            }
            uint32_t bfh[2][4], bfl[2][4];
            #pragma unroll
            for (int ng = 0; ng < 2; ng++) {
                int rowK = kf * 16 + (lane & 7) + ((lane >> 3) & 1) * 8;
                int cch  = ((wn0 + ng * 16) >> 3) + (lane >> 4);
                uint32_t so;
                if (NTILE == 128)
                    so = (uint32_t)(rowK * 256 +
                        ((((cch & 8) | ((cch ^ (rowK & 7)) & 7))) << 4));
                else
                    so = (uint32_t)(rowK * 128 + (((cch ^ (rowK & 7))) << 4));
                uint32_t a = st + OFF_B + so;
                LDSM_X4T(bfh[ng], a);
                LDSM_X4T(bfl[ng], a + BROWB * 32);
            }
            #pragma unroll
            for (int mf = 0; mf < MF; mf++)
                #pragma unroll
                for (int ng = 0; ng < 2; ng++) {
                    MMA16816(acc[mf][2 * ng],     afh[mf], bfh[ng][0], bfh[ng][1]);
                    MMA16816(acc[mf][2 * ng + 1], afh[mf], bfh[ng][2], bfh[ng][3]);
                }
            #pragma unroll
            for (int mf = 0; mf < MF; mf++)
                #pragma unroll
                for (int ng = 0; ng < 2; ng++) {
                    MMA16816(acc[mf][2 * ng],     afh[mf], bfl[ng][0], bfl[ng][1]);
                    MMA16816(acc[mf][2 * ng + 1], afh[mf], bfl[ng][2], bfl[ng][3]);
                }
            #pragma unroll
            for (int mf = 0; mf < MF; mf++)
                #pragma unroll
                for (int ng = 0; ng < 2; ng++) {
                    MMA16816(acc[mf][2 * ng],     afl[mf], bfh[ng][0], bfh[ng][1]);
                    MMA16816(acc[mf][2 * ng + 1], afl[mf], bfh[ng][2], bfh[ng][3]);
                }
        }
        __syncthreads();
    }

    // ---- epilogue
    #pragma unroll
    for (int mf = 0; mf < MF; mf++) {
        #pragma unroll
        for (int ng = 0; ng < 2; ng++) {
            #pragma unroll
            for (int nf = 0; nf < 2; nf++) {
                int col = wn0 + ng * 16 + nf * 8 + (lane & 3) * 2;
                #pragma unroll
                for (int half = 0; half < 2; half++) {
                    int r = m0 + wm0 + mf * 16 + (lane >> 2) + half * 8;
                    float v0 = acc[mf][2 * ng + nf][2 * half];
                    float v1 = acc[mf][2 * ng + nf][2 * half + 1];
                    if (EPI == 0) {
                        float b0 = (col < 32) ? bias[col] : bias2[col - 32];
                        float b1 = (col + 1 < 32) ? bias[col + 1] : bias2[col - 31];
                        v0 = fmaxf(v0 + b0, 0.0f);
                        v1 = fmaxf(v1 + b1, 0.0f);
                        uint32_t hp, lp;
                        split2(v0, v1, hp, lp);
                        if (col < 32) {
                            *(uint32_t*)&g_qh[(size_t)r * FQ + col] = hp;
                            *(uint32_t*)&g_ql[(size_t)r * FQ + col] = lp;
                        } else {
                            *(uint32_t*)&g_kh[(size_t)r * FQ + col - 32] = hp;
                            *(uint32_t*)&g_kl[(size_t)r * FQ + col - 32] = lp;
                        }
                    } else if (EPI == 1) {
                        int gc = n0 + col;
                        v0 = fmaxf(v0 + bias[gc], 0.0f);
                        v1 = fmaxf(v1 + bias[gc + 1], 0.0f);
                        __half2 h2 = __floats2half2_rn(v0, v1);
                        *(uint32_t*)&g_vf[(size_t)r * C + gc] = *(uint32_t*)&h2;
                    } else {
                        int gc = n0 + col;
                        float2 rr = *(const float2*)&resid[(size_t)r * C + gc];
                        float2 ov = make_float2(
                            fmaxf(v0 + bias[gc], 0.0f) + rr.x,
                            fmaxf(v1 + bias[gc + 1], 0.0f) + rr.y);
                        *(float2*)&out[(size_t)r * C + gc] = ov;
                    }
                }
            }
        }
    }
}

// Merged QK + V projection: grid (128, 3). y==0 -> QK, y in {1,2} -> V halves.
__global__ void __launch_bounds__(256) qkv_kernel(
    const __nv_bfloat16* __restrict__ xh, const __nv_bfloat16* __restrict__ xl,
    const float* __restrict__ bq, const float* __restrict__ bk,
    const float* __restrict__ bv)
{
    extern __shared__ char smem[];
    int m0 = blockIdx.x * 128;
    if (blockIdx.y == 0)
        gemm_body<64, 0>(xh, xl, g_wqkh, g_wqkl, bq, bk,
                         nullptr, nullptr, m0, 0, smem);
    else
        gemm_body<128, 1>(xh, xl, g_wvh, g_wvl, bv, nullptr,
                          nullptr, nullptr, m0, (blockIdx.y - 1) * 128, smem);
}

__global__ void __launch_bounds__(256) oproj_kernel(
    const float* __restrict__ bo, const float* __restrict__ resid,
    float* __restrict__ out)
{
    extern __shared__ char smem[];
    gemm_body<128, 2>(g_ah, g_al, g_woh, g_wol, bo, nullptr, resid, out,
                      blockIdx.x * 128, blockIdx.y * 128, smem);
}

// ---------------------------------------------------------------------------
// Flash attention: S = 3-term bf16 mma, ONLINE softmax (FMA-pipe exp,
// conditional rescale), PV = 1-term fp16 mma. 3-stage KV ring, 1 barrier/tile.
// CTA: 128 q-rows, 256 threads (8 warps x 16 rows x 256 cols).
// ---------------------------------------------------------------------------
#define KSWZ(row, c)  ((uint32_t)((row) * 64  + ((((c) ^ (((row) >> 1) & 3))) << 4)))
#define VSWZ(row, c)  ((uint32_t)((row) * 512 + ((((c) ^ ((row) & 7))) << 4)))

#define OFF_QH 0u
#define OFF_QL 8192u
#define OFF_ST 16384u
#define STAGE_SZ 40960u          /* KH 4K + KL 4K + VF 32K */
#define ATTN_SMEM (OFF_ST + 3 * STAGE_SZ)   /* 139264 B */

__global__ void __launch_bounds__(256, 1) attn_mma_kernel()
{
    extern __shared__ char smem[];
    const uint32_t sb = smem_u32(smem);
    const int tid  = threadIdx.x;
    const int lane = tid & 31;
    const int w    = tid >> 5;
    const int b    = blockIdx.y;
    const int q0   = blockIdx.x * 128;

    // ---- issue Q (group 1)
    {
        const __nv_bfloat16* qh = g_qh + (size_t)(b * NTOK + q0) * FQ;
        const __nv_bfloat16* ql = g_ql + (size_t)(b * NTOK + q0) * FQ;
        #pragma unroll
        for (int i = 0; i < 2; i++) {
            int idx = tid + 256 * i;
            int row = idx >> 2, c = idx & 3;
            CP_ASYNC16(sb + OFF_QH + KSWZ(row, c), qh + (size_t)row * FQ + c * 8);
            CP_ASYNC16(sb + OFF_QL + KSWZ(row, c), ql + (size_t)row * FQ + c * 8);
        }
        CP_COMMIT();
    }

    auto issue_kv = [&](int s, int t) {
        const uint32_t st = sb + OFF_ST + (uint32_t)s * STAGE_SZ;
        const size_t tok0 = (size_t)(b * NTOK + t * 64);
        {
            int row = tid >> 2, c = tid & 3;
            CP_ASYNC16(st + KSWZ(row, c),        g_kh + (tok0 + row) * FQ + c * 8);
            CP_ASYNC16(st + 4096 + KSWZ(row, c), g_kl + (tok0 + row) * FQ + c * 8);
        }
        #pragma unroll
        for (int i = 0; i < 8; i++) {
            int idx = tid + 256 * i;
            int row = idx >> 5, c = idx & 31;
            CP_ASYNC16(st + 8192 + VSWZ(row, c),
                       g_vf + (tok0 + row) * C + c * 8);
        }
        CP_COMMIT();
    };

    issue_kv(0, 0);          // group 2
    issue_kv(1, 1);          // group 3
    CP_WAIT(2);              // Q done
    __syncthreads();

    // ---- Q fragments (constant across tiles)
    uint32_t qa_h[2][4], qa_l[2][4];
    #pragma unroll
    for (int kc = 0; kc < 2; kc++) {
        int row = w * 16 + (lane & 15);
        int c   = kc * 2 + (lane >> 4);
        LDSM_X4(qa_h[kc], sb + OFF_QH + KSWZ(row, c));
        LDSM_X4(qa_l[kc], sb + OFF_QL + KSWZ(row, c));
    }

    float o[32][4];
    #pragma unroll
    for (int j = 0; j < 32; j++)
        #pragma unroll
        for (int e = 0; e < 4; e++) o[j][e] = 0.0f;
    float m0 = -1e30f, m1 = -1e30f, l0 = 0.0f, l1 = 0.0f;

    #pragma unroll 1
    for (int t = 0; t < 64; t++) {
        if (t + 1 < 64) { CP_WAIT(1); } else { CP_WAIT(0); }
        __syncthreads();                       // all warps done with stage t-1
        if (t + 2 < 64) issue_kv((t + 2) % 3, t + 2);

        const uint32_t st = sb + OFF_ST + (uint32_t)(t % 3) * STAGE_SZ;
        const uint32_t kh = st, kl = st + 4096, vf = st + 8192;

        // ---- S = Q K^T (3-term bf16)
        float sa[8][4];
        #pragma unroll
        for (int j = 0; j < 8; j++)
            #pragma unroll
            for (int e = 0; e < 4; e++) sa[j][e] = 0.0f;

        #pragma unroll
        for (int gk = 0; gk < 4; gk++) {
            int rowN = gk * 16 + (lane & 7) + ((lane >> 4) & 1) * 8;
            #pragma unroll
            for (int kc = 0; kc < 2; kc++) {
                int cc = kc * 2 + ((lane >> 3) & 1);
                uint32_t bh[4], bl[4];
                LDSM_X4(bh, kh + KSWZ(rowN, cc));
                LDSM_X4(bl, kl + KSWZ(rowN, cc));
                MMA16816(sa[2 * gk],     qa_h[kc], bh[0], bh[1]);
                MMA16816(sa[2 * gk + 1], qa_h[kc], bh[2], bh[3]);
                MMA16816(sa[2 * gk],     qa_h[kc], bl[0], bl[1]);
                MMA16816(sa[2 * gk + 1], qa_h[kc], bl[2], bl[3]);
                MMA16816(sa[2 * gk],     qa_l[kc], bh[0], bh[1]);
                MMA16816(sa[2 * gk + 1], qa_l[kc], bh[2], bh[3]);
            }
        }

        // ---- online softmax
        float tm0 = -1e30f, tm1 = -1e30f;
        #pragma unroll
        for (int j = 0; j < 8; j++) {
            tm0 = fmaxf(tm0, fmaxf(sa[j][0], sa[j][1]));
            tm1 = fmaxf(tm1, fmaxf(sa[j][2], sa[j][3]));
        }
        tm0 = fmaxf(tm0, __shfl_xor_sync(0xffffffffu, tm0, 1));
        tm0 = fmaxf(tm0, __shfl_xor_sync(0xffffffffu, tm0, 2));
        tm1 = fmaxf(tm1, __shfl_xor_sync(0xffffffffu, tm1, 1));
        tm1 = fmaxf(tm1, __shfl_xor_sync(0xffffffffu, tm1, 2));
        const float nm0 = fmaxf(m0, tm0), nm1 = fmaxf(m1, tm1);

        // conditional rescale: skip when no row got a new max
        if (nm0 > m0 || nm1 > m1) {
            const float sc0 = fexp(fmaxf(m0 - nm0, -80.0f));
            const float sc1 = fexp(fmaxf(m1 - nm1, -80.0f));
            l0 *= sc0; l1 *= sc1;
            #pragma unroll
            for (int j = 0; j < 32; j++) {
                o[j][0] *= sc0; o[j][1] *= sc0;
                o[j][2] *= sc1; o[j][3] *= sc1;
            }
        }
        m0 = nm0; m1 = nm1;

        uint32_t pf[4][4];
        #pragma unroll
        for (int kc = 0; kc < 4; kc++) {
            float p0 = fexp(sa[2 * kc][0]     - nm0);
            float p1 = fexp(sa[2 * kc][1]     - nm0);
            float p2 = fexp(sa[2 * kc][2]     - nm1);
            float p3 = fexp(sa[2 * kc][3]     - nm1);
            float p4 = fexp(sa[2 * kc + 1][0] - nm0);
            float p5 = fexp(sa[2 * kc + 1][1] - nm0);
            float p6 = fexp(sa[2 * kc + 1][2] - nm1);
            float p7 = fexp(sa[2 * kc + 1][3] - nm1);
            l0 += p0 + p1 + p4 + p5;
            l1 += p2 + p3 + p6 + p7;
            __half2 h2;
            h2 = __floats2half2_rn(p0, p1); pf[kc][0] = *(uint32_t*)&h2;
            h2 = __floats2half2_rn(p2, p3); pf[kc][1] = *(uint32_t*)&h2;
            h2 = __floats2half2_rn(p4, p5); pf[kc][2] = *(uint32_t*)&h2;
            h2 = __floats2half2_rn(p6, p7); pf[kc][3] = *(uint32_t*)&h2;
        }

        // ---- O += P V (single-term fp16)
        #pragma unroll
        for (int kc = 0; kc < 4; kc++) {
            int rowK = kc * 16 + (lane & 7) + ((lane >> 3) & 1) * 8;
            #pragma unroll
            for (int g = 0; g < 16; g++) {
                int cch = 2 * g + ((lane >> 4) & 1);
                uint32_t v4[4];
                LDSM_X4T(v4, vf + VSWZ(rowK, cch));
                MMAF16(o[2 * g],     pf[kc], v4[0], v4[1]);
                MMAF16(o[2 * g + 1], pf[kc], v4[2], v4[3]);
            }
        }
    }

    // ---- finalize
    l0 += __shfl_xor_sync(0xffffffffu, l0, 1);
    l0 += __shfl_xor_sync(0xffffffffu, l0, 2);
    l1 += __shfl_xor_sync(0xffffffffu, l1, 1);
    l1 += __shfl_xor_sync(0xffffffffu, l1, 2);
    const float inv0 = 1.0f / l0, inv1 = 1.0f / l1;

    const size_t r0 = (size_t)(b * NTOK + q0 + w * 16 + (lane >> 2));
    const size_t r1 = r0 + 8;
    #pragma unroll
    for (int j = 0; j < 32; j++) {
        int col = j * 8 + (lane & 3) * 2;
        uint32_t hp, lp;
        split2(o[j][0] * inv0, o[j][1] * inv0, hp, lp);
        *(uint32_t*)&g_ah[r0 * C + col] = hp;
        *(uint32_t*)&g_al[r0 * C + col] = lp;
        split2(o[j][2] * inv1, o[j][3] * inv1, hp, lp);
        *(uint32_t*)&g_ah[r1 * C + col] = hp;
        *(uint32_t*)&g_al[r1 * C + col] = lp;
    }
}

// ---------------------------------------------------------------------------
// Launch
// ---------------------------------------------------------------------------
extern "C" void kernel_launch(void* const* d_in, const int* in_sizes, int n_in,
                              void* d_out, int out_size)
{
    const float* x  = (const float*)d_in[0];
    const float* Wq = (const float*)d_in[1];
    const float* bq = (const float*)d_in[2];
    const float* Wk = (const float*)d_in[3];
    const float* bk = (const float*)d_in[4];
    const float* Wv = (const float*)d_in[5];
    const float* bv = (const float*)d_in[6];
    const float* Wo = (const float*)d_in[7];
    const float* bo = (const float*)d_in[8];
    float* out = (float*)d_out;

    __nv_bfloat16 *d_xh, *d_xl;
    cudaGetSymbolAddress((void**)&d_xh, g_xh);
    cudaGetSymbolAddress((void**)&d_xl, g_xl);

    constexpr uint32_t SMEM_G128 = 16384 + 2 * 256 * 32;   // 32 KB / stage
    cudaFuncSetAttribute(qkv_kernel,
        cudaFuncAttributeMaxDynamicSharedMemorySize, 2 * SMEM_G128);
    cudaFuncSetAttribute(oproj_kernel,
        cudaFuncAttributeMaxDynamicSharedMemorySize, 2 * SMEM_G128);
    cudaFuncSetAttribute(attn_mma_kernel,
        cudaFuncAttributeMaxDynamicSharedMemorySize, ATTN_SMEM);

    // 1. splits
    split_kernel<<<(NTOT * C / 2 + 255) / 256, 256>>>(x, d_xh, d_xl, NTOT * C / 2);
    split_weights_kernel<<<288, 256>>>(Wv, Wo, Wq, Wk);

    // 2. fused QK + V projections (one launch, 384 CTAs)
    qkv_kernel<<<dim3(128, 3), 256, 2 * SMEM_G128>>>(d_xh, d_xl, bq, bk, bv);

    // 3. attention (online softmax, FMA-pipe exp, fp16 PV)
    attn_mma_kernel<<<dim3(NTOK / 128, BATCH), 256, ATTN_SMEM>>>();

    // 4. output projection + relu + residual
    oproj_kernel<<<dim3(128, 2), 256, 2 * SMEM_G128>>>(bo, x, out);
}

// round 11
// speedup vs baseline: 1.0396x; 1.0396x over previous
#include <cuda_runtime.h>
#include <cuda_bf16.h>
#include <cuda_fp16.h>
#include <cstdint>
#include <math.h>

// Problem dims
#define BATCH 4
#define NTOK  4096
#define NTOT  16384
#define C     256
#define FQ    32

// Scratch (device globals; allocation-free)
__device__ __nv_bfloat16 g_xh[NTOT * C];
__device__ __nv_bfloat16 g_xl[NTOT * C];
__device__ __nv_bfloat16 g_wqkh[C * 64];
__device__ __nv_bfloat16 g_wqkl[C * 64];
__device__ __nv_bfloat16 g_wvh[C * C];
__device__ __nv_bfloat16 g_wvl[C * C];
__device__ __nv_bfloat16 g_woh[C * C];
__device__ __nv_bfloat16 g_wol[C * C];
__device__ __nv_bfloat16 g_qh[NTOT * FQ];
__device__ __nv_bfloat16 g_ql[NTOT * FQ];
__device__ __nv_bfloat16 g_kh[NTOT * FQ];
__device__ __nv_bfloat16 g_kl[NTOT * FQ];
__device__ __half        g_vf[NTOT * C];   // V as single fp16
__device__ __nv_bfloat16 g_ah[NTOT * C];   // attended hi
__device__ __nv_bfloat16 g_al[NTOT * C];   // attended lo

// ---------------------------------------------------------------------------
// Helpers
// ---------------------------------------------------------------------------
__device__ __forceinline__ uint32_t smem_u32(const void* p) {
    uint32_t a;
    asm("{ .reg .u64 t; cvta.to.shared.u64 t, %1; cvt.u32.u64 %0, t; }"
        : "=r"(a) : "l"(p));
    return a;
}

#define CP_ASYNC16(dst, src) \
    asm volatile("cp.async.cg.shared.global [%0], [%1], 16;" \
                 :: "r"(dst), "l"(src))
#define CP_COMMIT() asm volatile("cp.async.commit_group;" ::: "memory")
#define CP_WAIT(n)  asm volatile("cp.async.wait_group %0;" :: "n"(n) : "memory")

#define LDSM_X4(r, a) \
    asm volatile("ldmatrix.sync.aligned.m8n8.x4.shared.b16 {%0,%1,%2,%3}, [%4];" \
                 : "=r"((r)[0]), "=r"((r)[1]), "=r"((r)[2]), "=r"((r)[3]) : "r"(a))
#define LDSM_X4T(r, a) \
    asm volatile("ldmatrix.sync.aligned.m8n8.x4.trans.shared.b16 {%0,%1,%2,%3}, [%4];" \
                 : "=r"((r)[0]), "=r"((r)[1]), "=r"((r)[2]), "=r"((r)[3]) : "r"(a))

#define MMA16816(d, a, b0, b1) \
    asm volatile("mma.sync.aligned.m16n8k16.row.col.f32.bf16.bf16.f32 " \
                 "{%0,%1,%2,%3}, {%4,%5,%6,%7}, {%8,%9}, {%0,%1,%2,%3};" \
                 : "+f"((d)[0]), "+f"((d)[1]), "+f"((d)[2]), "+f"((d)[3]) \
                 : "r"((a)[0]), "r"((a)[1]), "r"((a)[2]), "r"((a)[3]), \
                   "r"(b0), "r"(b1))

#define MMAF16(d, a, b0, b1) \
    asm volatile("mma.sync.aligned.m16n8k16.row.col.f32.f16.f16.f32 " \
                 "{%0,%1,%2,%3}, {%4,%5,%6,%7}, {%8,%9}, {%0,%1,%2,%3};" \
                 : "+f"((d)[0]), "+f"((d)[1]), "+f"((d)[2]), "+f"((d)[3]) \
                 : "r"((a)[0]), "r"((a)[1]), "r"((a)[2]), "r"((a)[3]), \
                   "r"(b0), "r"(b1))

__device__ __forceinline__ void split2(float a, float b,
                                       uint32_t& hp, uint32_t& lp) {
    __nv_bfloat16 ha = __float2bfloat16(a);
    __nv_bfloat16 hb = __float2bfloat16(b);
    float la = a - __bfloat162float(ha);
    float lb = b - __bfloat162float(hb);
    __nv_bfloat162 hh; hh.x = ha; hh.y = hb;
    __nv_bfloat162 ll;
    ll.x = __float2bfloat16(la); ll.y = __float2bfloat16(lb);
    hp = *(uint32_t*)&hh;
    lp = *(uint32_t*)&ll;
}

// ---------------------------------------------------------------------------
// Split kernels (fp32 -> bf16 hi/lo)
// ---------------------------------------------------------------------------
__global__ void __launch_bounds__(256) split_kernel(
    const float* __restrict__ src, __nv_bfloat16* __restrict__ h,
    __nv_bfloat16* __restrict__ l, int n2)
{
    int i = blockIdx.x * 256 + threadIdx.x;
    if (i < n2) {
        float2 v = ((const float2*)src)[i];
        uint32_t hp, lp;
        split2(v.x, v.y, hp, lp);
        ((uint32_t*)h)[i] = hp;
        ((uint32_t*)l)[i] = lp;
    }
}

__global__ void __launch_bounds__(256) split_weights_kernel(
    const float* __restrict__ Wv, const float* __restrict__ Wo,
    const float* __restrict__ Wq, const float* __restrict__ Wk)
{
    int i2 = blockIdx.x * 256 + threadIdx.x;     // pair index
    if (i2 < 32768) {
        float2 v = ((const float2*)Wv)[i2];
        uint32_t hp, lp; split2(v.x, v.y, hp, lp);
        ((uint32_t*)g_wvh)[i2] = hp;
        ((uint32_t*)g_wvl)[i2] = lp;
    } else if (i2 < 65536) {
        int j = i2 - 32768;
        float2 v = ((const float2*)Wo)[j];
        uint32_t hp, lp; split2(v.x, v.y, hp, lp);
        ((uint32_t*)g_woh)[j] = hp;
        ((uint32_t*)g_wol)[j] = lp;
    } else if (i2 < 73728) {
        int j = i2 - 65536;
        int row = j >> 5;
        int col = (2 * j) & 63;
        float v0, v1;
        if (col < 32) { v0 = Wq[row * 32 + col];      v1 = Wq[row * 32 + col + 1]; }
        else          { v0 = Wk[row * 32 + col - 32]; v1 = Wk[row * 32 + col - 31]; }
        uint32_t hp, lp; split2(v0, v1, hp, lp);
        *(uint32_t*)&g_wqkh[row * 64 + col] = hp;
        *(uint32_t*)&g_wqkl[row * 64 + col] = lp;
    }
}

// ---------------------------------------------------------------------------
// bf16 mma GEMM body: out[rows m0..m0+127, N] = epi(A @ B), 3-term hi/lo.
// EPI: 0 = QK, 1 = V -> fp16, 2 = O -> fp32 + resid
// ---------------------------------------------------------------------------
#define ASWZ(row, c) ((uint32_t)((row) * 64 + ((((c) ^ (((row) >> 1) & 3))) << 4)))

template <int NTILE, int EPI>
__device__ __forceinline__ void gemm_body(
    const __nv_bfloat16* __restrict__ Ah, const __nv_bfloat16* __restrict__ Al,
    const __nv_bfloat16* __restrict__ Bh, const __nv_bfloat16* __restrict__ Bl,
    const float* __restrict__ bias, const float* __restrict__ bias2,
    const float* __restrict__ resid, float* __restrict__ out,
    int m0, int n0, char* smem)
{
    constexpr int NFULL = (EPI == 0) ? 64 : 256;
    constexpr int WNW = NTILE / 32;           // n-warps
    constexpr int WMW = 8 / WNW;              // m-warps
    constexpr int MF  = (128 / WMW) / 16;     // m-frags per warp
    constexpr int BROWB = NTILE * 2;          // B row bytes
    constexpr uint32_t OFF_B = 16384;
    constexpr uint32_t STAGE = OFF_B + 2 * (uint32_t)BROWB * 32;

    const uint32_t sb = smem_u32(smem);
    const int tid  = threadIdx.x;
    const int lane = tid & 31;
    const int w    = tid >> 5;
    const int wm0  = (w / WNW) * (128 / WMW);
    const int wn0  = (w % WNW) * 32;

    auto issue = [&](int s, int kt) {
        const uint32_t st = sb + (uint32_t)s * STAGE;
        #pragma unroll
        for (int i = 0; i < 2; i++) {
            int idx = tid + 256 * i;
            int row = idx >> 2, c = idx & 3;
            uint32_t so = ASWZ(row, c);
            const size_t ga = (size_t)(m0 + row) * 256 + kt * 32 + c * 8;
            CP_ASYNC16(st + so,        Ah + ga);
            CP_ASYNC16(st + 8192 + so, Al + ga);
        }
        if (NTILE == 128) {
            #pragma unroll
            for (int i = 0; i < 2; i++) {
                int idx = tid + 256 * i;
                int row = idx >> 4, c = idx & 15;
                uint32_t so = (uint32_t)(row * 256 +
                    ((((c & 8) | ((c ^ (row & 7)) & 7))) << 4));
                const size_t gb = (size_t)(kt * 32 + row) * NFULL + n0 + c * 8;
                CP_ASYNC16(st + OFF_B + so,              Bh + gb);
                CP_ASYNC16(st + OFF_B + BROWB * 32 + so, Bl + gb);
            }
        } else {
            int row = tid >> 3, c = tid & 7;
            uint32_t so = (uint32_t)(row * 128 + (((c ^ (row & 7))) << 4));
            const size_t gb = (size_t)(kt * 32 + row) * NFULL + n0 + c * 8;
            CP_ASYNC16(st + OFF_B + so,              Bh + gb);
            CP_ASYNC16(st + OFF_B + BROWB * 32 + so, Bl + gb);
        }
        CP_COMMIT();
    };

    float acc[MF][4][4];
    #pragma unroll
    for (int mf = 0; mf < MF; mf++)
        #pragma unroll
        for (int nf = 0; nf < 4; nf++)
            #pragma unroll
            for (int e = 0; e < 4; e++) acc[mf][nf][e] = 0.0f;

    issue(0, 0);

    #pragma unroll 1
    for (int kt = 0; kt < 8; kt++) {
        if (kt + 1 < 8) { issue((kt + 1) & 1, kt + 1); CP_WAIT(1); }
        else            { CP_WAIT(0); }
        __syncthreads();

        const uint32_t st = sb + (uint32_t)(kt & 1) * STAGE;

        #pragma unroll
        for (int kf = 0; kf < 2; kf++) {
            uint32_t afh[MF][4], afl[MF][4];
            #pragma unroll
            for (int mf = 0; mf < MF; mf++) {
                int row = wm0 + mf * 16 + (lane & 15);
                int c   = kf * 2 + (lane >> 4);
                uint32_t a = st + ASWZ(row, c);
                LDSM_X4(afh[mf], a);
                LDSM_X4(afl[mf], a + 8192);
            }
            uint32_t bfh[2][4], bfl[2][4];
            #pragma unroll
            for (int ng = 0; ng < 2; ng++) {
                int rowK = kf * 16 + (lane & 7) + ((lane >> 3) & 1) * 8;
                int cch  = ((wn0 + ng * 16) >> 3) + (lane >> 4);
                uint32_t so;
                if (NTILE == 128)
                    so = (uint32_t)(rowK * 256 +
                        ((((cch & 8) | ((cch ^ (rowK & 7)) & 7))) << 4));
                else
                    so = (uint32_t)(rowK * 128 + (((cch ^ (rowK & 7))) << 4));
                uint32_t a = st + OFF_B + so;
                LDSM_X4T(bfh[ng], a);
                LDSM_X4T(bfl[ng], a + BROWB * 32);
            }
            #pragma unroll
            for (int mf = 0; mf < MF; mf++)
                #pragma unroll
                for (int ng = 0; ng < 2; ng++) {
                    MMA16816(acc[mf][2 * ng],     afh[mf], bfh[ng][0], bfh[ng][1]);
                    MMA16816(acc[mf][2 * ng + 1], afh[mf], bfh[ng][2], bfh[ng][3]);
                }
            #pragma unroll
            for (int mf = 0; mf < MF; mf++)
                #pragma unroll
                for (int ng = 0; ng < 2; ng++) {
                    MMA16816(acc[mf][2 * ng],     afh[mf], bfl[ng][0], bfl[ng][1]);
                    MMA16816(acc[mf][2 * ng + 1], afh[mf], bfl[ng][2], bfl[ng][3]);
                }
            #pragma unroll
            for (int mf = 0; mf < MF; mf++)
                #pragma unroll
                for (int ng = 0; ng < 2; ng++) {
                    MMA16816(acc[mf][2 * ng],     afl[mf], bfh[ng][0], bfh[ng][1]);
                    MMA16816(acc[mf][2 * ng + 1], afl[mf], bfh[ng][2], bfh[ng][3]);
                }
        }
        __syncthreads();
    }

    // ---- epilogue
    #pragma unroll
    for (int mf = 0; mf < MF; mf++) {
        #pragma unroll
        for (int ng = 0; ng < 2; ng++) {
            #pragma unroll
            for (int nf = 0; nf < 2; nf++) {
                int col = wn0 + ng * 16 + nf * 8 + (lane & 3) * 2;
                #pragma unroll
                for (int half = 0; half < 2; half++) {
                    int r = m0 + wm0 + mf * 16 + (lane >> 2) + half * 8;
                    float v0 = acc[mf][2 * ng + nf][2 * half];
                    float v1 = acc[mf][2 * ng + nf][2 * half + 1];
                    if (EPI == 0) {
                        float b0 = (col < 32) ? bias[col] : bias2[col - 32];
                        float b1 = (col + 1 < 32) ? bias[col + 1] : bias2[col - 31];
                        v0 = fmaxf(v0 + b0, 0.0f);
                        v1 = fmaxf(v1 + b1, 0.0f);
                        uint32_t hp, lp;
                        split2(v0, v1, hp, lp);
                        if (col < 32) {
                            *(uint32_t*)&g_qh[(size_t)r * FQ + col] = hp;
                            *(uint32_t*)&g_ql[(size_t)r * FQ + col] = lp;
                        } else {
                            *(uint32_t*)&g_kh[(size_t)r * FQ + col - 32] = hp;
                            *(uint32_t*)&g_kl[(size_t)r * FQ + col - 32] = lp;
                        }
                    } else if (EPI == 1) {
                        int gc = n0 + col;
                        v0 = fmaxf(v0 + bias[gc], 0.0f);
                        v1 = fmaxf(v1 + bias[gc + 1], 0.0f);
                        __half2 h2 = __floats2half2_rn(v0, v1);
                        *(uint32_t*)&g_vf[(size_t)r * C + gc] = *(uint32_t*)&h2;
                    } else {
                        int gc = n0 + col;
                        float2 rr = *(const float2*)&resid[(size_t)r * C + gc];
                        float2 ov = make_float2(
                            fmaxf(v0 + bias[gc], 0.0f) + rr.x,
                            fmaxf(v1 + bias[gc + 1], 0.0f) + rr.y);
                        *(float2*)&out[(size_t)r * C + gc] = ov;
                    }
                }
            }
        }
    }
}

// Merged QK + V projection: grid (128, 3). y==0 -> QK, y in {1,2} -> V halves.
__global__ void __launch_bounds__(256) qkv_kernel(
    const __nv_bfloat16* __restrict__ xh, const __nv_bfloat16* __restrict__ xl,
    const float* __restrict__ bq, const float* __restrict__ bk,
    const float* __restrict__ bv)
{
    extern __shared__ char smem[];
    int m0 = blockIdx.x * 128;
    if (blockIdx.y == 0)
        gemm_body<64, 0>(xh, xl, g_wqkh, g_wqkl, bq, bk,
                         nullptr, nullptr, m0, 0, smem);
    else
        gemm_body<128, 1>(xh, xl, g_wvh, g_wvl, bv, nullptr,
                          nullptr, nullptr, m0, (blockIdx.y - 1) * 128, smem);
}

__global__ void __launch_bounds__(256) oproj_kernel(
    const float* __restrict__ bo, const float* __restrict__ resid,
    float* __restrict__ out)
{
    extern __shared__ char smem[];
    gemm_body<128, 2>(g_ah, g_al, g_woh, g_wol, bo, nullptr, resid, out,
                      blockIdx.x * 128, blockIdx.y * 128, smem);
}

// ---------------------------------------------------------------------------
// Flash attention, software-pipelined one tile deep:
//   per iter t:  S(t) MMAs  ->  rescale + PV(t-1) MMAs  ->  softmax(t)
// so softmax(t)'s latency is overlapped by S(t+1)'s independent MMAs.
// S = 3-term bf16 mma; PV = 1-term fp16 mma; 4-stage KV ring (V(t-1) must
// stay alive while K(t) is consumed). CTA: 128 q-rows, 256 threads.
// ---------------------------------------------------------------------------
#define KSWZ(row, c)  ((uint32_t)((row) * 64  + ((((c) ^ (((row) >> 1) & 3))) << 4)))
#define VSWZ(row, c)  ((uint32_t)((row) * 512 + ((((c) ^ ((row) & 7))) << 4)))

#define OFF_QH 0u
#define OFF_QL 8192u
#define OFF_ST 16384u
#define STAGE_SZ 40960u          /* KH 4K + KL 4K + VF 32K */
#define ATTN_SMEM (OFF_ST + 4 * STAGE_SZ)   /* 180224 B */

__global__ void __launch_bounds__(256, 1) attn_mma_kernel()
{
    extern __shared__ char smem[];
    const uint32_t sb = smem_u32(smem);
    const int tid  = threadIdx.x;
    const int lane = tid & 31;
    const int w    = tid >> 5;
    const int b    = blockIdx.y;
    const int q0   = blockIdx.x * 128;

    // ---- issue Q
    {
        const __nv_bfloat16* qh = g_qh + (size_t)(b * NTOK + q0) * FQ;
        const __nv_bfloat16* ql = g_ql + (size_t)(b * NTOK + q0) * FQ;
        #pragma unroll
        for (int i = 0; i < 2; i++) {
            int idx = tid + 256 * i;
            int row = idx >> 2, c = idx & 3;
            CP_ASYNC16(sb + OFF_QH + KSWZ(row, c), qh + (size_t)row * FQ + c * 8);
            CP_ASYNC16(sb + OFF_QL + KSWZ(row, c), ql + (size_t)row * FQ + c * 8);
        }
        CP_COMMIT();
    }

    auto issue_kv = [&](int s, int t) {
        const uint32_t st = sb + OFF_ST + (uint32_t)s * STAGE_SZ;
        const size_t tok0 = (size_t)(b * NTOK + t * 64);
        {
            int row = tid >> 2, c = tid & 3;
            CP_ASYNC16(st + KSWZ(row, c),        g_kh + (tok0 + row) * FQ + c * 8);
            CP_ASYNC16(st + 4096 + KSWZ(row, c), g_kl + (tok0 + row) * FQ + c * 8);
        }
        #pragma unroll
        for (int i = 0; i < 8; i++) {
            int idx = tid + 256 * i;
            int row = idx >> 5, c = idx & 31;
            CP_ASYNC16(st + 8192 + VSWZ(row, c),
                       g_vf + (tok0 + row) * C + c * 8);
        }
        CP_COMMIT();
    };

    issue_kv(0, 0);
    issue_kv(1, 1);
    CP_WAIT(2);              // Q done
    __syncthreads();

    // ---- Q fragments (constant across tiles)
    uint32_t qa_h[2][4], qa_l[2][4];
    #pragma unroll
    for (int kc = 0; kc < 2; kc++) {
        int row = w * 16 + (lane & 15);
        int c   = kc * 2 + (lane >> 4);
        LDSM_X4(qa_h[kc], sb + OFF_QH + KSWZ(row, c));
        LDSM_X4(qa_l[kc], sb + OFF_QL + KSWZ(row, c));
    }

    float o[32][4];
    #pragma unroll
    for (int j = 0; j < 32; j++)
        #pragma unroll
        for (int e = 0; e < 4; e++) o[j][e] = 0.0f;
    float m0 = -1e30f, m1 = -1e30f, l0 = 0.0f, l1 = 0.0f;
    float sc_p0 = 1.0f, sc_p1 = 1.0f;     // pending O rescale from softmax(t-1)
    uint32_t pf[4][4];                    // P(t-1) fragments (fp16)

    #pragma unroll 1
    for (int t = 0; t < 64; t++) {
        if (t + 1 < 64) { CP_WAIT(1); } else { CP_WAIT(0); }
        __syncthreads();                   // stage (t+2)%4 free to rewrite
        if (t + 2 < 64) issue_kv((t + 2) & 3, t + 2);

        const uint32_t stK = sb + OFF_ST + (uint32_t)(t & 3) * STAGE_SZ;
        const uint32_t kh = stK, kl = stK + 4096;

        // ---- S(t) = Q K^T (3-term bf16)
        float sa[8][4];
        #pragma unroll
        for (int j = 0; j < 8; j++)
            #pragma unroll
            for (int e = 0; e < 4; e++) sa[j][e] = 0.0f;

        #pragma unroll
        for (int gk = 0; gk < 4; gk++) {
            int rowN = gk * 16 + (lane & 7) + ((lane >> 4) & 1) * 8;
            #pragma unroll
            for (int kc = 0; kc < 2; kc++) {
                int cc = kc * 2 + ((lane >> 3) & 1);
                uint32_t bh[4], bl[4];
                LDSM_X4(bh, kh + KSWZ(rowN, cc));
                LDSM_X4(bl, kl + KSWZ(rowN, cc));
                MMA16816(sa[2 * gk],     qa_h[kc], bh[0], bh[1]);
                MMA16816(sa[2 * gk + 1], qa_h[kc], bh[2], bh[3]);
                MMA16816(sa[2 * gk],     qa_h[kc], bl[0], bl[1]);
                MMA16816(sa[2 * gk + 1], qa_h[kc], bl[2], bl[3]);
                MMA16816(sa[2 * gk],     qa_l[kc], bh[0], bh[1]);
                MMA16816(sa[2 * gk + 1], qa_l[kc], bh[2], bh[3]);
            }
        }

        // ---- rescale O + PV(t-1)  (V(t-1) stage still alive in the 4-ring)
        if (t > 0) {
            #pragma unroll
            for (int j = 0; j < 32; j++) {
                o[j][0] *= sc_p0; o[j][1] *= sc_p0;
                o[j][2] *= sc_p1; o[j][3] *= sc_p1;
            }
            const uint32_t vfp =
                sb + OFF_ST + (uint32_t)((t - 1) & 3) * STAGE_SZ + 8192;
            #pragma unroll
            for (int kc = 0; kc < 4; kc++) {
                int rowK = kc * 16 + (lane & 7) + ((lane >> 3) & 1) * 8;
                #pragma unroll
                for (int g = 0; g < 16; g++) {
                    int cch = 2 * g + ((lane >> 4) & 1);
                    uint32_t v4[4];
                    LDSM_X4T(v4, vfp + VSWZ(rowK, cch));
                    MMAF16(o[2 * g],     pf[kc], v4[0], v4[1]);
                    MMAF16(o[2 * g + 1], pf[kc], v4[2], v4[3]);
                }
            }
        }

        // ---- softmax(t): row max, sc, exp, fp16 pack (consumed next iter)
        float tm0 = -1e30f, tm1 = -1e30f;
        #pragma unroll
        for (int j = 0; j < 8; j++) {
            tm0 = fmaxf(tm0, fmaxf(sa[j][0], sa[j][1]));
            tm1 = fmaxf(tm1, fmaxf(sa[j][2], sa[j][3]));
        }
        tm0 = fmaxf(tm0, __shfl_xor_sync(0xffffffffu, tm0, 1));
        tm0 = fmaxf(tm0, __shfl_xor_sync(0xffffffffu, tm0, 2));
        tm1 = fmaxf(tm1, __shfl_xor_sync(0xffffffffu, tm1, 1));
        tm1 = fmaxf(tm1, __shfl_xor_sync(0xffffffffu, tm1, 2));
        const float nm0 = fmaxf(m0, tm0), nm1 = fmaxf(m1, tm1);
        sc_p0 = __expf(m0 - nm0);
        sc_p1 = __expf(m1 - nm1);
        m0 = nm0; m1 = nm1;
        l0 *= sc_p0; l1 *= sc_p1;

        #pragma unroll
        for (int kc = 0; kc < 4; kc++) {
            float p0 = __expf(sa[2 * kc][0]     - nm0);
            float p1 = __expf(sa[2 * kc][1]     - nm0);
            float p2 = __expf(sa[2 * kc][2]     - nm1);
            float p3 = __expf(sa[2 * kc][3]     - nm1);
            float p4 = __expf(sa[2 * kc + 1][0] - nm0);
            float p5 = __expf(sa[2 * kc + 1][1] - nm0);
            float p6 = __expf(sa[2 * kc + 1][2] - nm1);
            float p7 = __expf(sa[2 * kc + 1][3] - nm1);
            l0 += p0 + p1 + p4 + p5;
            l1 += p2 + p3 + p6 + p7;
            __half2 h2;
            h2 = __floats2half2_rn(p0, p1); pf[kc][0] = *(uint32_t*)&h2;
            h2 = __floats2half2_rn(p2, p3); pf[kc][1] = *(uint32_t*)&h2;
            h2 = __floats2half2_rn(p4, p5); pf[kc][2] = *(uint32_t*)&h2;
            h2 = __floats2half2_rn(p6, p7); pf[kc][3] = *(uint32_t*)&h2;
        }
    }

    // ---- tail: rescale + PV(63)
    {
        #pragma unroll
        for (int j = 0; j < 32; j++) {
            o[j][0] *= sc_p0; o[j][1] *= sc_p0;
            o[j][2] *= sc_p1; o[j][3] *= sc_p1;
        }
        const uint32_t vfp = sb + OFF_ST + (uint32_t)(63 & 3) * STAGE_SZ + 8192;
        #pragma unroll
        for (int kc = 0; kc < 4; kc++) {
            int rowK = kc * 16 + (lane & 7) + ((lane >> 3) & 1) * 8;
            #pragma unroll
            for (int g = 0; g < 16; g++) {
                int cch = 2 * g + ((lane >> 4) & 1);
                uint32_t v4[4];
                LDSM_X4T(v4, vfp + VSWZ(rowK, cch));
                MMAF16(o[2 * g],     pf[kc], v4[0], v4[1]);
                MMAF16(o[2 * g + 1], pf[kc], v4[2], v4[3]);
            }
        }
    }

    // ---- finalize
    l0 += __shfl_xor_sync(0xffffffffu, l0, 1);
    l0 += __shfl_xor_sync(0xffffffffu, l0, 2);
    l1 += __shfl_xor_sync(0xffffffffu, l1, 1);
    l1 += __shfl_xor_sync(0xffffffffu, l1, 2);
    const float inv0 = 1.0f / l0, inv1 = 1.0f / l1;

    const size_t r0 = (size_t)(b * NTOK + q0 + w * 16 + (lane >> 2));
    const size_t r1 = r0 + 8;
    #pragma unroll
    for (int j = 0; j < 32; j++) {
        int col = j * 8 + (lane & 3) * 2;
        uint32_t hp, lp;
        split2(o[j][0] * inv0, o[j][1] * inv0, hp, lp);
        *(uint32_t*)&g_ah[r0 * C + col] = hp;
        *(uint32_t*)&g_al[r0 * C + col] = lp;
        split2(o[j][2] * inv1, o[j][3] * inv1, hp, lp);
        *(uint32_t*)&g_ah[r1 * C + col] = hp;
        *(uint32_t*)&g_al[r1 * C + col] = lp;
    }
}

// ---------------------------------------------------------------------------
// Launch
// ---------------------------------------------------------------------------
extern "C" void kernel_launch(void* const* d_in, const int* in_sizes, int n_in,
                              void* d_out, int out_size)
{
    const float* x  = (const float*)d_in[0];
    const float* Wq = (const float*)d_in[1];
    const float* bq = (const float*)d_in[2];
    const float* Wk = (const float*)d_in[3];
    const float* bk = (const float*)d_in[4];
    const float* Wv = (const float*)d_in[5];
    const float* bv = (const float*)d_in[6];
    const float* Wo = (const float*)d_in[7];
    const float* bo = (const float*)d_in[8];
    float* out = (float*)d_out;

    __nv_bfloat16 *d_xh, *d_xl;
    cudaGetSymbolAddress((void**)&d_xh, g_xh);
    cudaGetSymbolAddress((void**)&d_xl, g_xl);

    constexpr uint32_t SMEM_G128 = 16384 + 2 * 256 * 32;   // 32 KB / stage
    cudaFuncSetAttribute(qkv_kernel,
        cudaFuncAttributeMaxDynamicSharedMemorySize, 2 * SMEM_G128);
    cudaFuncSetAttribute(oproj_kernel,
        cudaFuncAttributeMaxDynamicSharedMemorySize, 2 * SMEM_G128);
    cudaFuncSetAttribute(attn_mma_kernel,
        cudaFuncAttributeMaxDynamicSharedMemorySize, ATTN_SMEM);

    // 1. splits
    split_kernel<<<(NTOT * C / 2 + 255) / 256, 256>>>(x, d_xh, d_xl, NTOT * C / 2);
    split_weights_kernel<<<288, 256>>>(Wv, Wo, Wq, Wk);

    // 2. fused QK + V projections (one launch, 384 CTAs)
    qkv_kernel<<<dim3(128, 3), 256, 2 * SMEM_G128>>>(d_xh, d_xl, bq, bk, bv);

    // 3. attention (software-pipelined softmax hiding, fp16 PV)
    attn_mma_kernel<<<dim3(NTOK / 128, BATCH), 256, ATTN_SMEM>>>();

    // 4. output projection + relu + residual
    oproj_kernel<<<dim3(128, 2), 256, 2 * SMEM_G128>>>(bo, x, out);
}

// round 15
// speedup vs baseline: 1.0772x; 1.0361x over previous
#include <cuda_runtime.h>
#include <cuda_bf16.h>
#include <cuda_fp16.h>
#include <cstdint>
#include <math.h>

// Problem dims
#define BATCH 4
#define NTOK  4096
#define NTOT  16384
#define C     256
#define FQ    32

// Scratch (device globals; allocation-free)
__device__ __nv_bfloat16 g_xh[NTOT * C];
__device__ __nv_bfloat16 g_xl[NTOT * C];
__device__ __nv_bfloat16 g_wqkh[C * 64];
__device__ __nv_bfloat16 g_wqkl[C * 64];
__device__ __nv_bfloat16 g_wvh[C * C];
__device__ __nv_bfloat16 g_wvl[C * C];
__device__ __nv_bfloat16 g_woh[C * C];
__device__ __nv_bfloat16 g_wol[C * C];
__device__ __nv_bfloat16 g_qh[NTOT * FQ];
__device__ __nv_bfloat16 g_ql[NTOT * FQ];
__device__ __nv_bfloat16 g_kh[NTOT * FQ];
__device__ __nv_bfloat16 g_kl[NTOT * FQ];
__device__ __half        g_vf[NTOT * C];   // V as single fp16
__device__ __nv_bfloat16 g_ah[NTOT * C];   // attended hi
__device__ __nv_bfloat16 g_al[NTOT * C];   // attended lo

// ---------------------------------------------------------------------------
// Helpers
// ---------------------------------------------------------------------------
__device__ __forceinline__ uint32_t smem_u32(const void* p) {
    uint32_t a;
    asm("{ .reg .u64 t; cvta.to.shared.u64 t, %1; cvt.u32.u64 %0, t; }"
        : "=r"(a) : "l"(p));
    return a;
}

#define CP_ASYNC16(dst, src) \
    asm volatile("cp.async.cg.shared.global [%0], [%1], 16;" \
                 :: "r"(dst), "l"(src))
#define CP_COMMIT() asm volatile("cp.async.commit_group;" ::: "memory")
#define CP_WAIT(n)  asm volatile("cp.async.wait_group %0;" :: "n"(n) : "memory")

#define LDSM_X4(r, a) \
    asm volatile("ldmatrix.sync.aligned.m8n8.x4.shared.b16 {%0,%1,%2,%3}, [%4];" \
                 : "=r"((r)[0]), "=r"((r)[1]), "=r"((r)[2]), "=r"((r)[3]) : "r"(a))
#define LDSM_X4T(r, a) \
    asm volatile("ldmatrix.sync.aligned.m8n8.x4.trans.shared.b16 {%0,%1,%2,%3}, [%4];" \
                 : "=r"((r)[0]), "=r"((r)[1]), "=r"((r)[2]), "=r"((r)[3]) : "r"(a))

#define MMA16816(d, a, b0, b1) \
    asm volatile("mma.sync.aligned.m16n8k16.row.col.f32.bf16.bf16.f32 " \
                 "{%0,%1,%2,%3}, {%4,%5,%6,%7}, {%8,%9}, {%0,%1,%2,%3};" \
                 : "+f"((d)[0]), "+f"((d)[1]), "+f"((d)[2]), "+f"((d)[3]) \
                 : "r"((a)[0]), "r"((a)[1]), "r"((a)[2]), "r"((a)[3]), \
                   "r"(b0), "r"(b1))

#define MMAF16(d, a, b0, b1) \
    asm volatile("mma.sync.aligned.m16n8k16.row.col.f32.f16.f16.f32 " \
                 "{%0,%1,%2,%3}, {%4,%5,%6,%7}, {%8,%9}, {%0,%1,%2,%3};" \
                 : "+f"((d)[0]), "+f"((d)[1]), "+f"((d)[2]), "+f"((d)[3]) \
                 : "r"((a)[0]), "r"((a)[1]), "r"((a)[2]), "r"((a)[3]), \
                   "r"(b0), "r"(b1))

__device__ __forceinline__ void split2(float a, float b,
                                       uint32_t& hp, uint32_t& lp) {
    __nv_bfloat16 ha = __float2bfloat16(a);
    __nv_bfloat16 hb = __float2bfloat16(b);
    float la = a - __bfloat162float(ha);
    float lb = b - __bfloat162float(hb);
    __nv_bfloat162 hh; hh.x = ha; hh.y = hb;
    __nv_bfloat162 ll;
    ll.x = __float2bfloat16(la); ll.y = __float2bfloat16(lb);
    hp = *(uint32_t*)&hh;
    lp = *(uint32_t*)&ll;
}

// ---------------------------------------------------------------------------
// Split kernels (fp32 -> bf16 hi/lo)
// ---------------------------------------------------------------------------
__global__ void __launch_bounds__(256) split_kernel(
    const float* __restrict__ src, __nv_bfloat16* __restrict__ h,
    __nv_bfloat16* __restrict__ l, int n2)
{
    int i = blockIdx.x * 256 + threadIdx.x;
    if (i < n2) {
        float2 v = ((const float2*)src)[i];
        uint32_t hp, lp;
        split2(v.x, v.y, hp, lp);
        ((uint32_t*)h)[i] = hp;
        ((uint32_t*)l)[i] = lp;
    }
}

__global__ void __launch_bounds__(256) split_weights_kernel(
    const float* __restrict__ Wv, const float* __restrict__ Wo,
    const float* __restrict__ Wq, const float* __restrict__ Wk)
{
    int i2 = blockIdx.x * 256 + threadIdx.x;     // pair index
    if (i2 < 32768) {
        float2 v = ((const float2*)Wv)[i2];
        uint32_t hp, lp; split2(v.x, v.y, hp, lp);
        ((uint32_t*)g_wvh)[i2] = hp;
        ((uint32_t*)g_wvl)[i2] = lp;
    } else if (i2 < 65536) {
        int j = i2 - 32768;
        float2 v = ((const float2*)Wo)[j];
        uint32_t hp, lp; split2(v.x, v.y, hp, lp);
        ((uint32_t*)g_woh)[j] = hp;
        ((uint32_t*)g_wol)[j] = lp;
    } else if (i2 < 73728) {
        int j = i2 - 65536;
        int row = j >> 5;
        int col = (2 * j) & 63;
        float v0, v1;
        if (col < 32) { v0 = Wq[row * 32 + col];      v1 = Wq[row * 32 + col + 1]; }
        else          { v0 = Wk[row * 32 + col - 32]; v1 = Wk[row * 32 + col - 31]; }
        uint32_t hp, lp; split2(v0, v1, hp, lp);
        *(uint32_t*)&g_wqkh[row * 64 + col] = hp;
        *(uint32_t*)&g_wqkl[row * 64 + col] = lp;
    }
}

// ---------------------------------------------------------------------------
// bf16 mma GEMM body: out[rows m0..m0+127, N] = epi(A @ B), 3-term hi/lo.
// EPI: 0 = QK, 1 = V -> fp16, 2 = O -> fp32 + resid
// ---------------------------------------------------------------------------
#define ASWZ(row, c) ((uint32_t)((row) * 64 + ((((c) ^ (((row) >> 1) & 3))) << 4)))

template <int NTILE, int EPI>
__device__ __forceinline__ void gemm_body(
    const __nv_bfloat16* __restrict__ Ah, const __nv_bfloat16* __restrict__ Al,
    const __nv_bfloat16* __restrict__ Bh, const __nv_bfloat16* __restrict__ Bl,
    const float* __restrict__ bias, const float* __restrict__ bias2,
    const float* __restrict__ resid, float* __restrict__ out,
    int m0, int n0, char* smem)
{
    constexpr int NFULL = (EPI == 0) ? 64 : 256;
    constexpr int WNW = NTILE / 32;           // n-warps
    constexpr int WMW = 8 / WNW;              // m-warps
    constexpr int MF  = (128 / WMW) / 16;     // m-frags per warp
    constexpr int BROWB = NTILE * 2;          // B row bytes
    constexpr uint32_t OFF_B = 16384;
    constexpr uint32_t STAGE = OFF_B + 2 * (uint32_t)BROWB * 32;

    const uint32_t sb = smem_u32(smem);
    const int tid  = threadIdx.x;
    const int lane = tid & 31;
    const int w    = tid >> 5;
    const int wm0  = (w / WNW) * (128 / WMW);
    const int wn0  = (w % WNW) * 32;

    auto issue = [&](int s, int kt) {
        const uint32_t st = sb + (uint32_t)s * STAGE;
        #pragma unroll
        for (int i = 0; i < 2; i++) {
            int idx = tid + 256 * i;
            int row = idx >> 2, c = idx & 3;
            uint32_t so = ASWZ(row, c);
            const size_t ga = (size_t)(m0 + row) * 256 + kt * 32 + c * 8;
            CP_ASYNC16(st + so,        Ah + ga);
            CP_ASYNC16(st + 8192 + so, Al + ga);
        }
        if (NTILE == 128) {
            #pragma unroll
            for (int i = 0; i < 2; i++) {
                int idx = tid + 256 * i;
                int row = idx >> 4, c = idx & 15;
                uint32_t so = (uint32_t)(row * 256 +
                    ((((c & 8) | ((c ^ (row & 7)) & 7))) << 4));
                const size_t gb = (size_t)(kt * 32 + row) * NFULL + n0 + c * 8;
                CP_ASYNC16(st + OFF_B + so,              Bh + gb);
                CP_ASYNC16(st + OFF_B + BROWB * 32 + so, Bl + gb);
            }
        } else {
            int row = tid >> 3, c = tid & 7;
            uint32_t so = (uint32_t)(row * 128 + (((c ^ (row & 7))) << 4));
            const size_t gb = (size_t)(kt * 32 + row) * NFULL + n0 + c * 8;
            CP_ASYNC16(st + OFF_B + so,              Bh + gb);
            CP_ASYNC16(st + OFF_B + BROWB * 32 + so, Bl + gb);
        }
        CP_COMMIT();
    };

    float acc[MF][4][4];
    #pragma unroll
    for (int mf = 0; mf < MF; mf++)
        #pragma unroll
        for (int nf = 0; nf < 4; nf++)
            #pragma unroll
            for (int e = 0; e < 4; e++) acc[mf][nf][e] = 0.0f;

    issue(0, 0);

    #pragma unroll 1
    for (int kt = 0; kt < 8; kt++) {
        if (kt + 1 < 8) { issue((kt + 1) & 1, kt + 1); CP_WAIT(1); }
        else            { CP_WAIT(0); }
        __syncthreads();

        const uint32_t st = sb + (uint32_t)(kt & 1) * STAGE;

        #pragma unroll
        for (int kf = 0; kf < 2; kf++) {
            uint32_t afh[MF][4], afl[MF][4];
            #pragma unroll
            for (int mf = 0; mf < MF; mf++) {
                int row = wm0 + mf * 16 + (lane & 15);
                int c   = kf * 2 + (lane >> 4);
                uint32_t a = st + ASWZ(row, c);
                LDSM_X4(afh[mf], a);
                LDSM_X4(afl[mf], a + 8192);
            }
            uint32_t bfh[2][4], bfl[2][4];
            #pragma unroll
            for (int ng = 0; ng < 2; ng++) {
                int rowK = kf * 16 + (lane & 7) + ((lane >> 3) & 1) * 8;
                int cch  = ((wn0 + ng * 16) >> 3) + (lane >> 4);
                uint32_t so;
                if (NTILE == 128)
                    so = (uint32_t)(rowK * 256 +
                        ((((cch & 8) | ((cch ^ (rowK & 7)) & 7))) << 4));
                else
                    so = (uint32_t)(rowK * 128 + (((cch ^ (rowK & 7))) << 4));
                uint32_t a = st + OFF_B + so;
                LDSM_X4T(bfh[ng], a);
                LDSM_X4T(bfl[ng], a + BROWB * 32);
            }
            #pragma unroll
            for (int mf = 0; mf < MF; mf++)
                #pragma unroll
                for (int ng = 0; ng < 2; ng++) {
                    MMA16816(acc[mf][2 * ng],     afh[mf], bfh[ng][0], bfh[ng][1]);
                    MMA16816(acc[mf][2 * ng + 1], afh[mf], bfh[ng][2], bfh[ng][3]);
                }
            #pragma unroll
            for (int mf = 0; mf < MF; mf++)
                #pragma unroll
                for (int ng = 0; ng < 2; ng++) {
                    MMA16816(acc[mf][2 * ng],     afh[mf], bfl[ng][0], bfl[ng][1]);
                    MMA16816(acc[mf][2 * ng + 1], afh[mf], bfl[ng][2], bfl[ng][3]);
                }
            #pragma unroll
            for (int mf = 0; mf < MF; mf++)
                #pragma unroll
                for (int ng = 0; ng < 2; ng++) {
                    MMA16816(acc[mf][2 * ng],     afl[mf], bfh[ng][0], bfh[ng][1]);
                    MMA16816(acc[mf][2 * ng + 1], afl[mf], bfh[ng][2], bfh[ng][3]);
                }
        }
        __syncthreads();
    }

    // ---- epilogue
    #pragma unroll
    for (int mf = 0; mf < MF; mf++) {
        #pragma unroll
        for (int ng = 0; ng < 2; ng++) {
            #pragma unroll
            for (int nf = 0; nf < 2; nf++) {
                int col = wn0 + ng * 16 + nf * 8 + (lane & 3) * 2;
                #pragma unroll
                for (int half = 0; half < 2; half++) {
                    int r = m0 + wm0 + mf * 16 + (lane >> 2) + half * 8;
                    float v0 = acc[mf][2 * ng + nf][2 * half];
                    float v1 = acc[mf][2 * ng + nf][2 * half + 1];
                    if (EPI == 0) {
                        float b0 = (col < 32) ? bias[col] : bias2[col - 32];
                        float b1 = (col + 1 < 32) ? bias[col + 1] : bias2[col - 31];
                        v0 = fmaxf(v0 + b0, 0.0f);
                        v1 = fmaxf(v1 + b1, 0.0f);
                        uint32_t hp, lp;
                        split2(v0, v1, hp, lp);
                        if (col < 32) {
                            *(uint32_t*)&g_qh[(size_t)r * FQ + col] = hp;
                            *(uint32_t*)&g_ql[(size_t)r * FQ + col] = lp;
                        } else {
                            *(uint32_t*)&g_kh[(size_t)r * FQ + col - 32] = hp;
                            *(uint32_t*)&g_kl[(size_t)r * FQ + col - 32] = lp;
                        }
                    } else if (EPI == 1) {
                        int gc = n0 + col;
                        v0 = fmaxf(v0 + bias[gc], 0.0f);
                        v1 = fmaxf(v1 + bias[gc + 1], 0.0f);
                        __half2 h2 = __floats2half2_rn(v0, v1);
                        *(uint32_t*)&g_vf[(size_t)r * C + gc] = *(uint32_t*)&h2;
                    } else {
                        int gc = n0 + col;
                        float2 rr = *(const float2*)&resid[(size_t)r * C + gc];
                        float2 ov = make_float2(
                            fmaxf(v0 + bias[gc], 0.0f) + rr.x,
                            fmaxf(v1 + bias[gc + 1], 0.0f) + rr.y);
                        *(float2*)&out[(size_t)r * C + gc] = ov;
                    }
                }
            }
        }
    }
}

// Merged QK + V projection: grid (128, 3). y==0 -> QK, y in {1,2} -> V halves.
__global__ void __launch_bounds__(256) qkv_kernel(
    const __nv_bfloat16* __restrict__ xh, const __nv_bfloat16* __restrict__ xl,
    const float* __restrict__ bq, const float* __restrict__ bk,
    const float* __restrict__ bv)
{
    extern __shared__ char smem[];
    int m0 = blockIdx.x * 128;
    if (blockIdx.y == 0)
        gemm_body<64, 0>(xh, xl, g_wqkh, g_wqkl, bq, bk,
                         nullptr, nullptr, m0, 0, smem);
    else
        gemm_body<128, 1>(xh, xl, g_wvh, g_wvl, bv, nullptr,
                          nullptr, nullptr, m0, (blockIdx.y - 1) * 128, smem);
}

__global__ void __launch_bounds__(256) oproj_kernel(
    const float* __restrict__ bo, const float* __restrict__ resid,
    float* __restrict__ out)
{
    extern __shared__ char smem[];
    gemm_body<128, 2>(g_ah, g_al, g_woh, g_wol, bo, nullptr, resid, out,
                      blockIdx.x * 128, blockIdx.y * 128, smem);
}

// ---------------------------------------------------------------------------
// Flash attention, flash-style warp split with P staged through smem:
//   S/softmax: warp w owns rows 16w..16w+15 (as before).
//   PV:        warp w owns rows 64*(w>>2)..+63, cols 64*(w&3)..+63
//              (V reads per warp drop 4x; P read via ldmatrix from smem).
// Pipeline per iter t: S(t) -> rescale+PV(t-1) -> softmax(t) (+P/sc store).
// 4-stage KV ring; double-buffered P (fp16) + sc stages.
// ---------------------------------------------------------------------------
#define KSWZ(row, c)  ((uint32_t)((row) * 64  + ((((c) ^ (((row) >> 1) & 3))) << 4)))
#define VSWZ(row, c)  ((uint32_t)((row) * 512 + ((((c) ^ ((row) & 7))) << 4)))

#define OFF_QH 0u
#define OFF_QL 8192u
#define OFF_ST 16384u
#define STAGE_SZ 40960u                     /* KH 4K + KL 4K + VF 32K */
#define OFF_P  (OFF_ST + 4 * STAGE_SZ)      /* 180224; 2 x 16 KB P stages */
#define OFF_SC (OFF_P + 32768u)             /* 212992; 2 x 512 B sc stages */
#define OFF_L  (OFF_SC + 1024u)             /* 214016; 512 B l_s */
#define ATTN_SMEM (OFF_L + 512u)            /* 214528 B */

__global__ void __launch_bounds__(256, 1) attn_mma_kernel()
{
    extern __shared__ char smem[];
    const uint32_t sb = smem_u32(smem);
    const int tid  = threadIdx.x;
    const int lane = tid & 31;
    const int w    = tid >> 5;
    const int b    = blockIdx.y;
    const int q0   = blockIdx.x * 128;
    const int rgrp = (w >> 2) * 64;          // PV row base
    const int cgrp = (w & 3) * 64;           // PV col base

    // ---- issue Q
    {
        const __nv_bfloat16* qh = g_qh + (size_t)(b * NTOK + q0) * FQ;
        const __nv_bfloat16* ql = g_ql + (size_t)(b * NTOK + q0) * FQ;
        #pragma unroll
        for (int i = 0; i < 2; i++) {
            int idx = tid + 256 * i;
            int row = idx >> 2, c = idx & 3;
            CP_ASYNC16(sb + OFF_QH + KSWZ(row, c), qh + (size_t)row * FQ + c * 8);
            CP_ASYNC16(sb + OFF_QL + KSWZ(row, c), ql + (size_t)row * FQ + c * 8);
        }
        CP_COMMIT();
    }

    auto issue_kv = [&](int s, int t) {
        const uint32_t st = sb + OFF_ST + (uint32_t)s * STAGE_SZ;
        const size_t tok0 = (size_t)(b * NTOK + t * 64);
        {
            int row = tid >> 2, c = tid & 3;
            CP_ASYNC16(st + KSWZ(row, c),        g_kh + (tok0 + row) * FQ + c * 8);
            CP_ASYNC16(st + 4096 + KSWZ(row, c), g_kl + (tok0 + row) * FQ + c * 8);
        }
        #pragma unroll
        for (int i = 0; i < 8; i++) {
            int idx = tid + 256 * i;
            int row = idx >> 5, c = idx & 31;
            CP_ASYNC16(st + 8192 + VSWZ(row, c),
                       g_vf + (tok0 + row) * C + c * 8);
        }
        CP_COMMIT();
    };

    issue_kv(0, 0);
    issue_kv(1, 1);
    CP_WAIT(2);              // Q done
    __syncthreads();

    // ---- Q fragments (constant across tiles)
    uint32_t qa_h[2][4], qa_l[2][4];
    #pragma unroll
    for (int kc = 0; kc < 2; kc++) {
        int row = w * 16 + (lane & 15);
        int c   = kc * 2 + (lane >> 4);
        LDSM_X4(qa_h[kc], sb + OFF_QH + KSWZ(row, c));
        LDSM_X4(qa_l[kc], sb + OFF_QL + KSWZ(row, c));
    }

    float o[32][4];                          // o[mf*8+nf][e]
    #pragma unroll
    for (int j = 0; j < 32; j++)
        #pragma unroll
        for (int e = 0; e < 4; e++) o[j][e] = 0.0f;
    float m0 = -1e30f, m1 = -1e30f, l0 = 0.0f, l1 = 0.0f;
    const int r0 = w * 16 + (lane >> 2);     // softmax rows
    const int r1 = r0 + 8;

    // PV(t-1) block, also used for the tail
    auto pv_step = [&](int tm1) {
        const float* scp = (const float*)(smem + OFF_SC + (uint32_t)(tm1 & 1) * 512);
        #pragma unroll
        for (int mf = 0; mf < 4; mf++) {
            float s0 = scp[rgrp + mf * 16 + (lane >> 2)];
            float s1 = scp[rgrp + mf * 16 + 8 + (lane >> 2)];
            #pragma unroll
            for (int nf = 0; nf < 8; nf++) {
                o[mf * 8 + nf][0] *= s0; o[mf * 8 + nf][1] *= s0;
                o[mf * 8 + nf][2] *= s1; o[mf * 8 + nf][3] *= s1;
            }
        }
        const uint32_t pbp = sb + OFF_P + (uint32_t)(tm1 & 1) * 16384;
        const uint32_t vfp = sb + OFF_ST + (uint32_t)(tm1 & 3) * STAGE_SZ + 8192;
        #pragma unroll
        for (int kc = 0; kc < 4; kc++) {
            uint32_t pa[4][4];
            #pragma unroll
            for (int mf = 0; mf < 4; mf++) {
                int row = rgrp + mf * 16 + (lane & 15);
                int ch  = (kc * 2 + (lane >> 4)) ^ (row & 7);
                LDSM_X4(pa[mf], pbp + (uint32_t)(row * 128 + (ch << 4)));
            }
            int rowK = kc * 16 + (lane & 7) + ((lane >> 3) & 1) * 8;
            #pragma unroll
            for (int ng = 0; ng < 4; ng++) {
                int cch = (cgrp >> 3) + 2 * ng + ((lane >> 4) & 1);
                uint32_t v4[4];
                LDSM_X4T(v4, vfp + VSWZ(rowK, cch));
                #pragma unroll
                for (int mf = 0; mf < 4; mf++) {
                    MMAF16(o[mf * 8 + 2 * ng],     pa[mf], v4[0], v4[1]);
                    MMAF16(o[mf * 8 + 2 * ng + 1], pa[mf], v4[2], v4[3]);
                }
            }
        }
    };

    #pragma unroll 1
    for (int t = 0; t < 64; t++) {
        if (t + 1 < 64) { CP_WAIT(1); } else { CP_WAIT(0); }
        __syncthreads();      // orders: P/sc(t-1) writes, V(t-1) readers done
        if (t + 2 < 64) issue_kv((t + 2) & 3, t + 2);

        const uint32_t stK = sb + OFF_ST + (uint32_t)(t & 3) * STAGE_SZ;
        const uint32_t kh = stK, kl = stK + 4096;

        // ---- S(t) = Q K^T (3-term bf16), rows 16w
        float sa[8][4];
        #pragma unroll
        for (int j = 0; j < 8; j++)
            #pragma unroll
            for (int e = 0; e < 4; e++) sa[j][e] = 0.0f;

        #pragma unroll
        for (int gk = 0; gk < 4; gk++) {
            int rowN = gk * 16 + (lane & 7) + ((lane >> 4) & 1) * 8;
            #pragma unroll
            for (int kc = 0; kc < 2; kc++) {
                int cc = kc * 2 + ((lane >> 3) & 1);
                uint32_t bh[4], bl[4];
                LDSM_X4(bh, kh + KSWZ(rowN, cc));
                LDSM_X4(bl, kl + KSWZ(rowN, cc));
                MMA16816(sa[2 * gk],     qa_h[kc], bh[0], bh[1]);
                MMA16816(sa[2 * gk + 1], qa_h[kc], bh[2], bh[3]);
                MMA16816(sa[2 * gk],     qa_h[kc], bl[0], bl[1]);
                MMA16816(sa[2 * gk + 1], qa_h[kc], bl[2], bl[3]);
                MMA16816(sa[2 * gk],     qa_l[kc], bh[0], bh[1]);
                MMA16816(sa[2 * gk + 1], qa_l[kc], bh[2], bh[3]);
            }
        }

        // ---- rescale + PV(t-1)
        if (t > 0) pv_step(t - 1);

        // ---- softmax(t): rows 16w; store P(t), sc(t)
        float tm0 = -1e30f, tm1 = -1e30f;
        #pragma unroll
        for (int j = 0; j < 8; j++) {
            tm0 = fmaxf(tm0, fmaxf(sa[j][0], sa[j][1]));
            tm1 = fmaxf(tm1, fmaxf(sa[j][2], sa[j][3]));
        }
        tm0 = fmaxf(tm0, __shfl_xor_sync(0xffffffffu, tm0, 1));
        tm0 = fmaxf(tm0, __shfl_xor_sync(0xffffffffu, tm0, 2));
        tm1 = fmaxf(tm1, __shfl_xor_sync(0xffffffffu, tm1, 1));
        tm1 = fmaxf(tm1, __shfl_xor_sync(0xffffffffu, tm1, 2));
        const float nm0 = fmaxf(m0, tm0), nm1 = fmaxf(m1, tm1);
        const float sc0 = __expf(m0 - nm0), sc1 = __expf(m1 - nm1);
        m0 = nm0; m1 = nm1;
        l0 *= sc0; l1 *= sc1;

        float* scs = (float*)(smem + OFF_SC + (uint32_t)(t & 1) * 512);
        if ((lane & 3) == 0) { scs[r0] = sc0; scs[r1] = sc1; }

        const uint32_t pbw = sb + OFF_P + (uint32_t)(t & 1) * 16384;
        const uint32_t w0 = (uint32_t)(r0 * 128) + (uint32_t)((lane & 3) * 4);
        const uint32_t w1 = (uint32_t)(r1 * 128) + (uint32_t)((lane & 3) * 4);
        #pragma unroll
        for (int kc = 0; kc < 4; kc++) {
            float p0 = __expf(sa[2 * kc][0]     - nm0);
            float p1 = __expf(sa[2 * kc][1]     - nm0);
            float p2 = __expf(sa[2 * kc][2]     - nm1);
            float p3 = __expf(sa[2 * kc][3]     - nm1);
            float p4 = __expf(sa[2 * kc + 1][0] - nm0);
            float p5 = __expf(sa[2 * kc + 1][1] - nm0);
            float p6 = __expf(sa[2 * kc + 1][2] - nm1);
            float p7 = __expf(sa[2 * kc + 1][3] - nm1);
            l0 += p0 + p1 + p4 + p5;
            l1 += p2 + p3 + p6 + p7;
            __half2 h2;
            uint32_t u;
            int c0 = 2 * kc, c1 = 2 * kc + 1;
            h2 = __floats2half2_rn(p0, p1); u = *(uint32_t*)&h2;
            *(uint32_t*)(smem + pbw - sb + w0 + ((c0 ^ (r0 & 7)) << 4)) = u;
            h2 = __floats2half2_rn(p2, p3); u = *(uint32_t*)&h2;
            *(uint32_t*)(smem + pbw - sb + w1 + ((c0 ^ (r1 & 7)) << 4)) = u;
            h2 = __floats2half2_rn(p4, p5); u = *(uint32_t*)&h2;
            *(uint32_t*)(smem + pbw - sb + w0 + ((c1 ^ (r0 & 7)) << 4)) = u;
            h2 = __floats2half2_rn(p6, p7); u = *(uint32_t*)&h2;
            *(uint32_t*)(smem + pbw - sb + w1 + ((c1 ^ (r1 & 7)) << 4)) = u;
        }
    }

    // ---- tail: PV(63)
    __syncthreads();
    pv_step(63);

    // ---- finalize: publish l, then scale + store
    l0 += __shfl_xor_sync(0xffffffffu, l0, 1);
    l0 += __shfl_xor_sync(0xffffffffu, l0, 2);
    l1 += __shfl_xor_sync(0xffffffffu, l1, 1);
    l1 += __shfl_xor_sync(0xffffffffu, l1, 2);
    float* ls = (float*)(smem + OFF_L);
    if ((lane & 3) == 0) { ls[r0] = l0; ls[r1] = l1; }
    __syncthreads();

    #pragma unroll
    for (int mf = 0; mf < 4; mf++) {
        const float inv0 = 1.0f / ls[rgrp + mf * 16 + (lane >> 2)];
        const float inv1 = 1.0f / ls[rgrp + mf * 16 + 8 + (lane >> 2)];
        const size_t rowA = (size_t)(b * NTOK + q0 + rgrp + mf * 16 + (lane >> 2));
        const size_t rowB = rowA + 8;
        #pragma unroll
        for (int nf = 0; nf < 8; nf++) {
            int col = cgrp + nf * 8 + (lane & 3) * 2;
            uint32_t hp, lp;
            split2(o[mf * 8 + nf][0] * inv0, o[mf * 8 + nf][1] * inv0, hp, lp);
            *(uint32_t*)&g_ah[rowA * C + col] = hp;
            *(uint32_t*)&g_al[rowA * C + col] = lp;
            split2(o[mf * 8 + nf][2] * inv1, o[mf * 8 + nf][3] * inv1, hp, lp);
            *(uint32_t*)&g_ah[rowB * C + col] = hp;
            *(uint32_t*)&g_al[rowB * C + col] = lp;
        }
    }
}

// ---------------------------------------------------------------------------
// Launch
// ---------------------------------------------------------------------------
extern "C" void kernel_launch(void* const* d_in, const int* in_sizes, int n_in,
                              void* d_out, int out_size)
{
    const float* x  = (const float*)d_in[0];
    const float* Wq = (const float*)d_in[1];
    const float* bq = (const float*)d_in[2];
    const float* Wk = (const float*)d_in[3];
    const float* bk = (const float*)d_in[4];
    const float* Wv = (const float*)d_in[5];
    const float* bv = (const float*)d_in[6];
    const float* Wo = (const float*)d_in[7];
    const float* bo = (const float*)d_in[8];
    float* out = (float*)d_out;

    __nv_bfloat16 *d_xh, *d_xl;
    cudaGetSymbolAddress((void**)&d_xh, g_xh);
    cudaGetSymbolAddress((void**)&d_xl, g_xl);

    constexpr uint32_t SMEM_G128 = 16384 + 2 * 256 * 32;   // 32 KB / stage
    cudaFuncSetAttribute(qkv_kernel,
        cudaFuncAttributeMaxDynamicSharedMemorySize, 2 * SMEM_G128);
    cudaFuncSetAttribute(oproj_kernel,
        cudaFuncAttributeMaxDynamicSharedMemorySize, 2 * SMEM_G128);
    cudaFuncSetAttribute(attn_mma_kernel,
        cudaFuncAttributeMaxDynamicSharedMemorySize, ATTN_SMEM);

    // 1. splits
    split_kernel<<<(NTOT * C / 2 + 255) / 256, 256>>>(x, d_xh, d_xl, NTOT * C / 2);
    split_weights_kernel<<<288, 256>>>(Wv, Wo, Wq, Wk);

    // 2. fused QK + V projections (one launch, 384 CTAs)
    qkv_kernel<<<dim3(128, 3), 256, 2 * SMEM_G128>>>(d_xh, d_xl, bq, bk, bv);

    // 3. attention (flash warp split, P through smem, fp16 PV)
    attn_mma_kernel<<<dim3(NTOK / 128, BATCH), 256, ATTN_SMEM>>>();

    // 4. output projection + relu + residual
    oproj_kernel<<<dim3(128, 2), 256, 2 * SMEM_G128>>>(bo, x, out);
}

// round 16
// speedup vs baseline: 1.1188x; 1.0386x over previous
#include <cuda_runtime.h>
#include <cuda_bf16.h>
#include <cuda_fp16.h>
#include <cstdint>
#include <math.h>

// Problem dims
#define BATCH 4
#define NTOK  4096
#define NTOT  16384
#define C     256
#define FQ    32

// Scratch (device globals; allocation-free)
__device__ __nv_bfloat16 g_xh[NTOT * C];
__device__ __nv_bfloat16 g_xl[NTOT * C];
__device__ __nv_bfloat16 g_wqkh[C * 64];
__device__ __nv_bfloat16 g_wqkl[C * 64];
__device__ __nv_bfloat16 g_wvh[C * C];
__device__ __nv_bfloat16 g_wvl[C * C];
__device__ __nv_bfloat16 g_woh[C * C];
__device__ __nv_bfloat16 g_wol[C * C];
__device__ __nv_bfloat16 g_qh[NTOT * FQ];
__device__ __nv_bfloat16 g_ql[NTOT * FQ];
__device__ __nv_bfloat16 g_kh[NTOT * FQ];
__device__ __nv_bfloat16 g_kl[NTOT * FQ];
__device__ __half        g_vf[NTOT * C];   // V as single fp16

// ---------------------------------------------------------------------------
// Helpers
// ---------------------------------------------------------------------------
__device__ __forceinline__ uint32_t smem_u32(const void* p) {
    uint32_t a;
    asm("{ .reg .u64 t; cvta.to.shared.u64 t, %1; cvt.u32.u64 %0, t; }"
        : "=r"(a) : "l"(p));
    return a;
}

#define CP_ASYNC16(dst, src) \
    asm volatile("cp.async.cg.shared.global [%0], [%1], 16;" \
                 :: "r"(dst), "l"(src))
#define CP_COMMIT() asm volatile("cp.async.commit_group;" ::: "memory")
#define CP_WAIT(n)  asm volatile("cp.async.wait_group %0;" :: "n"(n) : "memory")

#define LDSM_X4(r, a) \
    asm volatile("ldmatrix.sync.aligned.m8n8.x4.shared.b16 {%0,%1,%2,%3}, [%4];" \
                 : "=r"((r)[0]), "=r"((r)[1]), "=r"((r)[2]), "=r"((r)[3]) : "r"(a))
#define LDSM_X4T(r, a) \
    asm volatile("ldmatrix.sync.aligned.m8n8.x4.trans.shared.b16 {%0,%1,%2,%3}, [%4];" \
                 : "=r"((r)[0]), "=r"((r)[1]), "=r"((r)[2]), "=r"((r)[3]) : "r"(a))

#define MMA16816(d, a, b0, b1) \
    asm volatile("mma.sync.aligned.m16n8k16.row.col.f32.bf16.bf16.f32 " \
                 "{%0,%1,%2,%3}, {%4,%5,%6,%7}, {%8,%9}, {%0,%1,%2,%3};" \
                 : "+f"((d)[0]), "+f"((d)[1]), "+f"((d)[2]), "+f"((d)[3]) \
                 : "r"((a)[0]), "r"((a)[1]), "r"((a)[2]), "r"((a)[3]), \
                   "r"(b0), "r"(b1))

#define MMAF16(d, a, b0, b1) \
    asm volatile("mma.sync.aligned.m16n8k16.row.col.f32.f16.f16.f32 " \
                 "{%0,%1,%2,%3}, {%4,%5,%6,%7}, {%8,%9}, {%0,%1,%2,%3};" \
                 : "+f"((d)[0]), "+f"((d)[1]), "+f"((d)[2]), "+f"((d)[3]) \
                 : "r"((a)[0]), "r"((a)[1]), "r"((a)[2]), "r"((a)[3]), \
                   "r"(b0), "r"(b1))

__device__ __forceinline__ void split2(float a, float b,
                                       uint32_t& hp, uint32_t& lp) {
    __nv_bfloat16 ha = __float2bfloat16(a);
    __nv_bfloat16 hb = __float2bfloat16(b);
    float la = a - __bfloat162float(ha);
    float lb = b - __bfloat162float(hb);
    __nv_bfloat162 hh; hh.x = ha; hh.y = hb;
    __nv_bfloat162 ll;
    ll.x = __float2bfloat16(la); ll.y = __float2bfloat16(lb);
    hp = *(uint32_t*)&hh;
    lp = *(uint32_t*)&ll;
}

// ---------------------------------------------------------------------------
// Split kernels (fp32 -> bf16 hi/lo)
// ---------------------------------------------------------------------------
__global__ void __launch_bounds__(256) split_kernel(
    const float* __restrict__ src, __nv_bfloat16* __restrict__ h,
    __nv_bfloat16* __restrict__ l, int n2)
{
    int i = blockIdx.x * 256 + threadIdx.x;
    if (i < n2) {
        float2 v = ((const float2*)src)[i];
        uint32_t hp, lp;
        split2(v.x, v.y, hp, lp);
        ((uint32_t*)h)[i] = hp;
        ((uint32_t*)l)[i] = lp;
    }
}

__global__ void __launch_bounds__(256) split_weights_kernel(
    const float* __restrict__ Wv, const float* __restrict__ Wo,
    const float* __restrict__ Wq, const float* __restrict__ Wk)
{
    int i2 = blockIdx.x * 256 + threadIdx.x;     // pair index
    if (i2 < 32768) {
        float2 v = ((const float2*)Wv)[i2];
        uint32_t hp, lp; split2(v.x, v.y, hp, lp);
        ((uint32_t*)g_wvh)[i2] = hp;
        ((uint32_t*)g_wvl)[i2] = lp;
    } else if (i2 < 65536) {
        int j = i2 - 32768;
        float2 v = ((const float2*)Wo)[j];
        uint32_t hp, lp; split2(v.x, v.y, hp, lp);
        ((uint32_t*)g_woh)[j] = hp;
        ((uint32_t*)g_wol)[j] = lp;
    } else if (i2 < 73728) {
        int j = i2 - 65536;
        int row = j >> 5;
        int col = (2 * j) & 63;
        float v0, v1;
        if (col < 32) { v0 = Wq[row * 32 + col];      v1 = Wq[row * 32 + col + 1]; }
        else          { v0 = Wk[row * 32 + col - 32]; v1 = Wk[row * 32 + col - 31]; }
        uint32_t hp, lp; split2(v0, v1, hp, lp);
        *(uint32_t*)&g_wqkh[row * 64 + col] = hp;
        *(uint32_t*)&g_wqkl[row * 64 + col] = lp;
    }
}

// ---------------------------------------------------------------------------
// bf16 mma GEMM body (projections): 3-term hi/lo.
// EPI: 0 = QK (N=64, relu+bias, split), 1 = V (N=256, relu+bias -> fp16)
// ---------------------------------------------------------------------------
#define ASWZ(row, c) ((uint32_t)((row) * 64 + ((((c) ^ (((row) >> 1) & 3))) << 4)))

template <int NTILE, int EPI>
__device__ __forceinline__ void gemm_body(
    const __nv_bfloat16* __restrict__ Ah, const __nv_bfloat16* __restrict__ Al,
    const __nv_bfloat16* __restrict__ Bh, const __nv_bfloat16* __restrict__ Bl,
    const float* __restrict__ bias, const float* __restrict__ bias2,
    int m0, int n0, char* smem)
{
    constexpr int NFULL = (EPI == 0) ? 64 : 256;
    constexpr int WNW = NTILE / 32;
    constexpr int WMW = 8 / WNW;
    constexpr int MF  = (128 / WMW) / 16;
    constexpr int BROWB = NTILE * 2;
    constexpr uint32_t OFF_B = 16384;
    constexpr uint32_t STAGE = OFF_B + 2 * (uint32_t)BROWB * 32;

    const uint32_t sb = smem_u32(smem);
    const int tid  = threadIdx.x;
    const int lane = tid & 31;
    const int w    = tid >> 5;
    const int wm0  = (w / WNW) * (128 / WMW);
    const int wn0  = (w % WNW) * 32;

    auto issue = [&](int s, int kt) {
        const uint32_t st = sb + (uint32_t)s * STAGE;
        #pragma unroll
        for (int i = 0; i < 2; i++) {
            int idx = tid + 256 * i;
            int row = idx >> 2, c = idx & 3;
            uint32_t so = ASWZ(row, c);
            const size_t ga = (size_t)(m0 + row) * 256 + kt * 32 + c * 8;
            CP_ASYNC16(st + so,        Ah + ga);
            CP_ASYNC16(st + 8192 + so, Al + ga);
        }
        if (NTILE == 128) {
            #pragma unroll
            for (int i = 0; i < 2; i++) {
                int idx = tid + 256 * i;
                int row = idx >> 4, c = idx & 15;
                uint32_t so = (uint32_t)(row * 256 +
                    ((((c & 8) | ((c ^ (row & 7)) & 7))) << 4));
                const size_t gb = (size_t)(kt * 32 + row) * NFULL + n0 + c * 8;
                CP_ASYNC16(st + OFF_B + so,              Bh + gb);
                CP_ASYNC16(st + OFF_B + BROWB * 32 + so, Bl + gb);
            }
        } else {
            int row = tid >> 3, c = tid & 7;
            uint32_t so = (uint32_t)(row * 128 + (((c ^ (row & 7))) << 4));
            const size_t gb = (size_t)(kt * 32 + row) * NFULL + n0 + c * 8;
            CP_ASYNC16(st + OFF_B + so,              Bh + gb);
            CP_ASYNC16(st + OFF_B + BROWB * 32 + so, Bl + gb);
        }
        CP_COMMIT();
    };

    float acc[MF][4][4];
    #pragma unroll
    for (int mf = 0; mf < MF; mf++)
        #pragma unroll
        for (int nf = 0; nf < 4; nf++)
            #pragma unroll
            for (int e = 0; e < 4; e++) acc[mf][nf][e] = 0.0f;

    issue(0, 0);

    #pragma unroll 1
    for (int kt = 0; kt < 8; kt++) {
        if (kt + 1 < 8) { issue((kt + 1) & 1, kt + 1); CP_WAIT(1); }
        else            { CP_WAIT(0); }
        __syncthreads();

        const uint32_t st = sb + (uint32_t)(kt & 1) * STAGE;

        #pragma unroll
        for (int kf = 0; kf < 2; kf++) {
            uint32_t afh[MF][4], afl[MF][4];
            #pragma unroll
            for (int mf = 0; mf < MF; mf++) {
                int row = wm0 + mf * 16 + (lane & 15);
                int c   = kf * 2 + (lane >> 4);
                uint32_t a = st + ASWZ(row, c);
                LDSM_X4(afh[mf], a);
                LDSM_X4(afl[mf], a + 8192);
            }
            uint32_t bfh[2][4], bfl[2][4];
            #pragma unroll
            for (int ng = 0; ng < 2; ng++) {
                int rowK = kf * 16 + (lane & 7) + ((lane >> 3) & 1) * 8;
                int cch  = ((wn0 + ng * 16) >> 3) + (lane >> 4);
                uint32_t so;
                if (NTILE == 128)
                    so = (uint32_t)(rowK * 256 +
                        ((((cch & 8) | ((cch ^ (rowK & 7)) & 7))) << 4));
                else
                    so = (uint32_t)(rowK * 128 + (((cch ^ (rowK & 7))) << 4));
                uint32_t a = st + OFF_B + so;
                LDSM_X4T(bfh[ng], a);
                LDSM_X4T(bfl[ng], a + BROWB * 32);
            }
            #pragma unroll
            for (int mf = 0; mf < MF; mf++)
                #pragma unroll
                for (int ng = 0; ng < 2; ng++) {
                    MMA16816(acc[mf][2 * ng],     afh[mf], bfh[ng][0], bfh[ng][1]);
                    MMA16816(acc[mf][2 * ng + 1], afh[mf], bfh[ng][2], bfh[ng][3]);
                }
            #pragma unroll
            for (int mf = 0; mf < MF; mf++)
                #pragma unroll
                for (int ng = 0; ng < 2; ng++) {
                    MMA16816(acc[mf][2 * ng],     afh[mf], bfl[ng][0], bfl[ng][1]);
                    MMA16816(acc[mf][2 * ng + 1], afh[mf], bfl[ng][2], bfl[ng][3]);
                }
            #pragma unroll
            for (int mf = 0; mf < MF; mf++)
                #pragma unroll
                for (int ng = 0; ng < 2; ng++) {
                    MMA16816(acc[mf][2 * ng],     afl[mf], bfh[ng][0], bfh[ng][1]);
                    MMA16816(acc[mf][2 * ng + 1], afl[mf], bfh[ng][2], bfh[ng][3]);
                }
        }
        __syncthreads();
    }

    // ---- epilogue
    #pragma unroll
    for (int mf = 0; mf < MF; mf++) {
        #pragma unroll
        for (int ng = 0; ng < 2; ng++) {
            #pragma unroll
            for (int nf = 0; nf < 2; nf++) {
                int col = wn0 + ng * 16 + nf * 8 + (lane & 3) * 2;
                #pragma unroll
                for (int half = 0; half < 2; half++) {
                    int r = m0 + wm0 + mf * 16 + (lane >> 2) + half * 8;
                    float v0 = acc[mf][2 * ng + nf][2 * half];
                    float v1 = acc[mf][2 * ng + nf][2 * half + 1];
                    if (EPI == 0) {
                        float b0 = (col < 32) ? bias[col] : bias2[col - 32];
                        float b1 = (col + 1 < 32) ? bias[col + 1] : bias2[col - 31];
                        v0 = fmaxf(v0 + b0, 0.0f);
                        v1 = fmaxf(v1 + b1, 0.0f);
                        uint32_t hp, lp;
                        split2(v0, v1, hp, lp);
                        if (col < 32) {
                            *(uint32_t*)&g_qh[(size_t)r * FQ + col] = hp;
                            *(uint32_t*)&g_ql[(size_t)r * FQ + col] = lp;
                        } else {
                            *(uint32_t*)&g_kh[(size_t)r * FQ + col - 32] = hp;
                            *(uint32_t*)&g_kl[(size_t)r * FQ + col - 32] = lp;
                        }
                    } else {
                        int gc = n0 + col;
                        v0 = fmaxf(v0 + bias[gc], 0.0f);
                        v1 = fmaxf(v1 + bias[gc + 1], 0.0f);
                        __half2 h2 = __floats2half2_rn(v0, v1);
                        *(uint32_t*)&g_vf[(size_t)r * C + gc] = *(uint32_t*)&h2;
                    }
                }
            }
        }
    }
}

// Merged QK + V projection: grid (128, 3). y==0 -> QK, y in {1,2} -> V halves.
__global__ void __launch_bounds__(256) qkv_kernel(
    const __nv_bfloat16* __restrict__ xh, const __nv_bfloat16* __restrict__ xl,
    const float* __restrict__ bq, const float* __restrict__ bk,
    const float* __restrict__ bv)
{
    extern __shared__ char smem[];
    int m0 = blockIdx.x * 128;
    if (blockIdx.y == 0)
        gemm_body<64, 0>(xh, xl, g_wqkh, g_wqkl, bq, bk, m0, 0, smem);
    else
        gemm_body<128, 1>(xh, xl, g_wvh, g_wvl, bv, nullptr,
                          m0, (blockIdx.y - 1) * 128, smem);
}

// ---------------------------------------------------------------------------
// Fused attention + output projection.
// Phase 1 (flash attention): as R15 (warp-split PV, P through smem, lazy
// rescale). Phase 2: O (normalized, bf16 hi/lo) -> smem A-tiles; 3-term
// GEMM with Wo streamed via cp.async; relu+bias+residual -> out.
// ---------------------------------------------------------------------------
#define KSWZ(row, c)  ((uint32_t)((row) * 64  + ((((c) ^ (((row) >> 1) & 3))) << 4)))
#define VSWZ(row, c)  ((uint32_t)((row) * 512 + ((((c) ^ ((row) & 7))) << 4)))

#define OFF_QH 0u
#define OFF_QL 8192u
#define OFF_ST 16384u
#define STAGE_SZ 40960u                     /* KH 4K + KL 4K + VF 32K */
#define OFF_P  (OFF_ST + 4 * STAGE_SZ)      /* 180224; 2 x 16 KB P stages */
#define OFF_SC (OFF_P + 32768u)             /* 212992; 2 x 512 B sc stages */
#define OFF_L  (OFF_SC + 1024u)             /* 214016; 512 B l_s */
#define ATTN_SMEM (OFF_L + 512u)            /* 214528 B */

// Phase-2 layout (after KV loop; regions dead by then):
//   A hi: 0..65536 (8 ktiles x 8 KB, ASWZ), A lo: 65536..131072
//   B stages: 131072 + s*32768 (hi 16 KB + lo 16 KB), s in {0,1}
#define OFF2_AH 0u
#define OFF2_AL 65536u
#define OFF2_B  131072u

__global__ void __launch_bounds__(256, 1) attn_mma_kernel(
    const float* __restrict__ xres, const float* __restrict__ bo,
    float* __restrict__ out)
{
    extern __shared__ char smem[];
    const uint32_t sb = smem_u32(smem);
    const int tid  = threadIdx.x;
    const int lane = tid & 31;
    const int w    = tid >> 5;
    const int b    = blockIdx.y;
    const int q0   = blockIdx.x * 128;
    const int rgrp = (w >> 2) * 64;          // PV / phase-2 row base
    const int cgrp = (w & 3) * 64;           // PV / phase-2 col base

    // ---- issue Q
    {
        const __nv_bfloat16* qh = g_qh + (size_t)(b * NTOK + q0) * FQ;
        const __nv_bfloat16* ql = g_ql + (size_t)(b * NTOK + q0) * FQ;
        #pragma unroll
        for (int i = 0; i < 2; i++) {
            int idx = tid + 256 * i;
            int row = idx >> 2, c = idx & 3;
            CP_ASYNC16(sb + OFF_QH + KSWZ(row, c), qh + (size_t)row * FQ + c * 8);
            CP_ASYNC16(sb + OFF_QL + KSWZ(row, c), ql + (size_t)row * FQ + c * 8);
        }
        CP_COMMIT();
    }

    auto issue_kv = [&](int s, int t) {
        const uint32_t st = sb + OFF_ST + (uint32_t)s * STAGE_SZ;
        const size_t tok0 = (size_t)(b * NTOK + t * 64);
        {
            int row = tid >> 2, c = tid & 3;
            CP_ASYNC16(st + KSWZ(row, c),        g_kh + (tok0 + row) * FQ + c * 8);
            CP_ASYNC16(st + 4096 + KSWZ(row, c), g_kl + (tok0 + row) * FQ + c * 8);
        }
        #pragma unroll
        for (int i = 0; i < 8; i++) {
            int idx = tid + 256 * i;
            int row = idx >> 5, c = idx & 31;
            CP_ASYNC16(st + 8192 + VSWZ(row, c),
                       g_vf + (tok0 + row) * C + c * 8);
        }
        CP_COMMIT();
    };

    issue_kv(0, 0);
    issue_kv(1, 1);
    CP_WAIT(2);              // Q done
    __syncthreads();

    // ---- Q fragments (constant across tiles)
    uint32_t qa_h[2][4], qa_l[2][4];
    #pragma unroll
    for (int kc = 0; kc < 2; kc++) {
        int row = w * 16 + (lane & 15);
        int c   = kc * 2 + (lane >> 4);
        LDSM_X4(qa_h[kc], sb + OFF_QH + KSWZ(row, c));
        LDSM_X4(qa_l[kc], sb + OFF_QL + KSWZ(row, c));
    }

    float o[32][4];                          // o[mf*8+nf][e]
    #pragma unroll
    for (int j = 0; j < 32; j++)
        #pragma unroll
        for (int e = 0; e < 4; e++) o[j][e] = 0.0f;
    float m0 = -1e30f, m1 = -1e30f, l0 = 0.0f, l1 = 0.0f;
    const int r0 = w * 16 + (lane >> 2);     // softmax rows
    const int r1 = r0 + 8;

    // PV(t-1) block with lazy O-rescale
    auto pv_step = [&](int tm1) {
        const float* scp = (const float*)(smem + OFF_SC + (uint32_t)(tm1 & 1) * 512);
        float s0v[4], s1v[4];
        bool ne = false;
        #pragma unroll
        for (int mf = 0; mf < 4; mf++) {
            s0v[mf] = scp[rgrp + mf * 16 + (lane >> 2)];
            s1v[mf] = scp[rgrp + mf * 16 + 8 + (lane >> 2)];
            ne |= (s0v[mf] != 1.0f) | (s1v[mf] != 1.0f);
        }
        if (__ballot_sync(0xffffffffu, ne)) {
            #pragma unroll
            for (int mf = 0; mf < 4; mf++)
                #pragma unroll
                for (int nf = 0; nf < 8; nf++) {
                    o[mf * 8 + nf][0] *= s0v[mf]; o[mf * 8 + nf][1] *= s0v[mf];
                    o[mf * 8 + nf][2] *= s1v[mf]; o[mf * 8 + nf][3] *= s1v[mf];
                }
        }
        const uint32_t pbp = sb + OFF_P + (uint32_t)(tm1 & 1) * 16384;
        const uint32_t vfp = sb + OFF_ST + (uint32_t)(tm1 & 3) * STAGE_SZ + 8192;
        #pragma unroll
        for (int kc = 0; kc < 4; kc++) {
            uint32_t pa[4][4];
            #pragma unroll
            for (int mf = 0; mf < 4; mf++) {
                int row = rgrp + mf * 16 + (lane & 15);
                int ch  = (kc * 2 + (lane >> 4)) ^ (row & 7);
                LDSM_X4(pa[mf], pbp + (uint32_t)(row * 128 + (ch << 4)));
            }
            int rowK = kc * 16 + (lane & 7) + ((lane >> 3) & 1) * 8;
            #pragma unroll
            for (int ng = 0; ng < 4; ng++) {
                int cch = (cgrp >> 3) + 2 * ng + ((lane >> 4) & 1);
                uint32_t v4[4];
                LDSM_X4T(v4, vfp + VSWZ(rowK, cch));
                #pragma unroll
                for (int mf = 0; mf < 4; mf++) {
                    MMAF16(o[mf * 8 + 2 * ng],     pa[mf], v4[0], v4[1]);
                    MMAF16(o[mf * 8 + 2 * ng + 1], pa[mf], v4[2], v4[3]);
                }
            }
        }
    };

    #pragma unroll 1
    for (int t = 0; t < 64; t++) {
        if (t + 1 < 64) { CP_WAIT(1); } else { CP_WAIT(0); }
        __syncthreads();
        if (t + 2 < 64) issue_kv((t + 2) & 3, t + 2);

        const uint32_t stK = sb + OFF_ST + (uint32_t)(t & 3) * STAGE_SZ;
        const uint32_t kh = stK, kl = stK + 4096;

        // ---- S(t) = Q K^T (3-term bf16), rows 16w
        float sa[8][4];
        #pragma unroll
        for (int j = 0; j < 8; j++)
            #pragma unroll
            for (int e = 0; e < 4; e++) sa[j][e] = 0.0f;

        #pragma unroll
        for (int gk = 0; gk < 4; gk++) {
            int rowN = gk * 16 + (lane & 7) + ((lane >> 4) & 1) * 8;
            #pragma unroll
            for (int kc = 0; kc < 2; kc++) {
                int cc = kc * 2 + ((lane >> 3) & 1);
                uint32_t bh[4], bl[4];
                LDSM_X4(bh, kh + KSWZ(rowN, cc));
                LDSM_X4(bl, kl + KSWZ(rowN, cc));
                MMA16816(sa[2 * gk],     qa_h[kc], bh[0], bh[1]);
                MMA16816(sa[2 * gk + 1], qa_h[kc], bh[2], bh[3]);
                MMA16816(sa[2 * gk],     qa_h[kc], bl[0], bl[1]);
                MMA16816(sa[2 * gk + 1], qa_h[kc], bl[2], bl[3]);
                MMA16816(sa[2 * gk],     qa_l[kc], bh[0], bh[1]);
                MMA16816(sa[2 * gk + 1], qa_l[kc], bh[2], bh[3]);
            }
        }

        // ---- rescale + PV(t-1)
        if (t > 0) pv_step(t - 1);

        // ---- softmax(t): rows 16w; store P(t), sc(t)
        float tm0 = -1e30f, tm1 = -1e30f;
        #pragma unroll
        for (int j = 0; j < 8; j++) {
            tm0 = fmaxf(tm0, fmaxf(sa[j][0], sa[j][1]));
            tm1 = fmaxf(tm1, fmaxf(sa[j][2], sa[j][3]));
        }
        tm0 = fmaxf(tm0, __shfl_xor_sync(0xffffffffu, tm0, 1));
        tm0 = fmaxf(tm0, __shfl_xor_sync(0xffffffffu, tm0, 2));
        tm1 = fmaxf(tm1, __shfl_xor_sync(0xffffffffu, tm1, 1));
        tm1 = fmaxf(tm1, __shfl_xor_sync(0xffffffffu, tm1, 2));
        const float nm0 = fmaxf(m0, tm0), nm1 = fmaxf(m1, tm1);
        const float sc0 = (nm0 > m0) ? __expf(m0 - nm0) : 1.0f;
        const float sc1 = (nm1 > m1) ? __expf(m1 - nm1) : 1.0f;
        m0 = nm0; m1 = nm1;
        l0 *= sc0; l1 *= sc1;

        float* scs = (float*)(smem + OFF_SC + (uint32_t)(t & 1) * 512);
        if ((lane & 3) == 0) { scs[r0] = sc0; scs[r1] = sc1; }

        const uint32_t pbw = sb + OFF_P + (uint32_t)(t & 1) * 16384;
        const uint32_t w0 = (uint32_t)(r0 * 128) + (uint32_t)((lane & 3) * 4);
        const uint32_t w1 = (uint32_t)(r1 * 128) + (uint32_t)((lane & 3) * 4);
        #pragma unroll
        for (int kc = 0; kc < 4; kc++) {
            float p0 = __expf(sa[2 * kc][0]     - nm0);
            float p1 = __expf(sa[2 * kc][1]     - nm0);
            float p2 = __expf(sa[2 * kc][2]     - nm1);
            float p3 = __expf(sa[2 * kc][3]     - nm1);
            float p4 = __expf(sa[2 * kc + 1][0] - nm0);
            float p5 = __expf(sa[2 * kc + 1][1] - nm0);
            float p6 = __expf(sa[2 * kc + 1][2] - nm1);
            float p7 = __expf(sa[2 * kc + 1][3] - nm1);
            l0 += p0 + p1 + p4 + p5;
            l1 += p2 + p3 + p6 + p7;
            __half2 h2;
            uint32_t u;
            int c0 = 2 * kc, c1 = 2 * kc + 1;
            h2 = __floats2half2_rn(p0, p1); u = *(uint32_t*)&h2;
            *(uint32_t*)(smem + pbw - sb + w0 + ((c0 ^ (r0 & 7)) << 4)) = u;
            h2 = __floats2half2_rn(p2, p3); u = *(uint32_t*)&h2;
            *(uint32_t*)(smem + pbw - sb + w1 + ((c0 ^ (r1 & 7)) << 4)) = u;
            h2 = __floats2half2_rn(p4, p5); u = *(uint32_t*)&h2;
            *(uint32_t*)(smem + pbw - sb + w0 + ((c1 ^ (r0 & 7)) << 4)) = u;
            h2 = __floats2half2_rn(p6, p7); u = *(uint32_t*)&h2;
            *(uint32_t*)(smem + pbw - sb + w1 + ((c1 ^ (r1 & 7)) << 4)) = u;
        }
    }

    // ---- tail: PV(63)
    __syncthreads();
    pv_step(63);

    // ---- publish l
    l0 += __shfl_xor_sync(0xffffffffu, l0, 1);
    l0 += __shfl_xor_sync(0xffffffffu, l0, 2);
    l1 += __shfl_xor_sync(0xffffffffu, l1, 1);
    l1 += __shfl_xor_sync(0xffffffffu, l1, 2);
    float* ls = (float*)(smem + OFF_L);
    if ((lane & 3) == 0) { ls[r0] = l0; ls[r1] = l1; }
    __syncthreads();

    // ================= phase 2: fused output projection =================
    // Store normalized O as bf16 hi/lo A-tiles (ASWZ layout, 8 ktiles).
    #pragma unroll
    for (int mf = 0; mf < 4; mf++) {
        const float inv0 = 1.0f / ls[rgrp + mf * 16 + (lane >> 2)];
        const float inv1 = 1.0f / ls[rgrp + mf * 16 + 8 + (lane >> 2)];
        const int rowA = rgrp + mf * 16 + (lane >> 2);
        const int rowB = rowA + 8;
        #pragma unroll
        for (int nf = 0; nf < 8; nf++) {
            int col = cgrp + nf * 8 + (lane & 3) * 2;
            int kt = col >> 5, chunk = (col & 31) >> 3, bi = (col & 7) * 2;
            uint32_t baseA = (uint32_t)(kt * 8192) + ASWZ(rowA, chunk) + bi;
            uint32_t baseB = (uint32_t)(kt * 8192) + ASWZ(rowB, chunk) + bi;
            uint32_t hp, lp;
            split2(o[mf * 8 + nf][0] * inv0, o[mf * 8 + nf][1] * inv0, hp, lp);
            *(uint32_t*)(smem + OFF2_AH + baseA) = hp;
            *(uint32_t*)(smem + OFF2_AL + baseA) = lp;
            split2(o[mf * 8 + nf][2] * inv1, o[mf * 8 + nf][3] * inv1, hp, lp);
            *(uint32_t*)(smem + OFF2_AH + baseB) = hp;
            *(uint32_t*)(smem + OFF2_AL + baseB) = lp;
        }
    }

    // B (Wo) streaming: 32 rows x 512 B per stage (hi + lo)
    auto issue_B = [&](int s, int kt) {
        const uint32_t st = sb + OFF2_B + (uint32_t)s * 32768;
        #pragma unroll
        for (int i = 0; i < 4; i++) {
            int idx = tid + 256 * i;
            int row = idx >> 5, c = idx & 31;
            uint32_t so = (uint32_t)(row * 512 +
                ((((c & 24) | ((c ^ (row & 7)) & 7))) << 4));
            const size_t gb = (size_t)(kt * 32 + row) * 256 + c * 8;
            CP_ASYNC16(st + so,         g_woh + gb);
            CP_ASYNC16(st + 16384 + so, g_wol + gb);
        }
        CP_COMMIT();
    };

    float acc[4][8][4];
    #pragma unroll
    for (int mf = 0; mf < 4; mf++)
        #pragma unroll
        for (int nf = 0; nf < 8; nf++)
            #pragma unroll
            for (int e = 0; e < 4; e++) acc[mf][nf][e] = 0.0f;

    issue_B(0, 0);
    __syncthreads();         // A-tiles visible to all warps

    #pragma unroll 1
    for (int kt = 0; kt < 8; kt++) {
        if (kt + 1 < 8) { issue_B((kt + 1) & 1, kt + 1); CP_WAIT(1); }
        else            { CP_WAIT(0); }
        __syncthreads();

        const uint32_t stB = sb + OFF2_B + (uint32_t)(kt & 1) * 32768;
        const uint32_t stA = sb + (uint32_t)(kt * 8192);

        #pragma unroll
        for (int kf = 0; kf < 2; kf++) {
            uint32_t afh[4][4], afl[4][4];
            #pragma unroll
            for (int mf = 0; mf < 4; mf++) {
                int row = rgrp + mf * 16 + (lane & 15);
                int c   = kf * 2 + (lane >> 4);
                uint32_t a = stA + ASWZ(row, c);
                LDSM_X4(afh[mf], a);
                LDSM_X4(afl[mf], a + 65536);
            }
            int rowK = kf * 16 + (lane & 7) + ((lane >> 3) & 1) * 8;
            #pragma unroll
            for (int ng = 0; ng < 4; ng++) {
                int cch = (cgrp >> 3) + 2 * ng + (lane >> 4);
                uint32_t so = (uint32_t)(rowK * 512 +
                    ((((cch & 24) | ((cch ^ (rowK & 7)) & 7))) << 4));
                uint32_t bfh[4], bfl[4];
                LDSM_X4T(bfh, stB + so);
                LDSM_X4T(bfl, stB + 16384 + so);
                #pragma unroll
                for (int mf = 0; mf < 4; mf++) {
                    MMA16816(acc[mf][2 * ng],     afh[mf], bfh[0], bfh[1]);
                    MMA16816(acc[mf][2 * ng + 1], afh[mf], bfh[2], bfh[3]);
                    MMA16816(acc[mf][2 * ng],     afh[mf], bfl[0], bfl[1]);
                    MMA16816(acc[mf][2 * ng + 1], afh[mf], bfl[2], bfl[3]);
                    MMA16816(acc[mf][2 * ng],     afl[mf], bfh[0], bfh[1]);
                    MMA16816(acc[mf][2 * ng + 1], afl[mf], bfh[2], bfh[3]);
                }
            }
        }
        __syncthreads();
    }

    // ---- epilogue: relu + bias + residual -> out
    #pragma unroll
    for (int mf = 0; mf < 4; mf++) {
        #pragma unroll
        for (int ng = 0; ng < 4; ng++) {
            #pragma unroll
            for (int nf = 0; nf < 2; nf++) {
                int col = cgrp + ng * 16 + nf * 8 + (lane & 3) * 2;
                #pragma unroll
                for (int half = 0; half < 2; half++) {
                    size_t gr = (size_t)(b * NTOK + q0 + rgrp + mf * 16 +
                                         (lane >> 2) + half * 8);
                    float v0 = acc[mf][2 * ng + nf][2 * half];
                    float v1 = acc[mf][2 * ng + nf][2 * half + 1];
                    float2 rr = *(const float2*)&xres[gr * C + col];
                    float2 ov = make_float2(
                        fmaxf(v0 + bo[col], 0.0f) + rr.x,
                        fmaxf(v1 + bo[col + 1], 0.0f) + rr.y);
                    *(float2*)&out[gr * C + col] = ov;
                }
            }
        }
    }
}

// ---------------------------------------------------------------------------
// Launch
// ---------------------------------------------------------------------------
extern "C" void kernel_launch(void* const* d_in, const int* in_sizes, int n_in,
                              void* d_out, int out_size)
{
    const float* x  = (const float*)d_in[0];
    const float* Wq = (const float*)d_in[1];
    const float* bq = (const float*)d_in[2];
    const float* Wk = (const float*)d_in[3];
    const float* bk = (const float*)d_in[4];
    const float* Wv = (const float*)d_in[5];
    const float* bv = (const float*)d_in[6];
    const float* Wo = (const float*)d_in[7];
    const float* bo = (const float*)d_in[8];
    float* out = (float*)d_out;

    __nv_bfloat16 *d_xh, *d_xl;
    cudaGetSymbolAddress((void**)&d_xh, g_xh);
    cudaGetSymbolAddress((void**)&d_xl, g_xl);

    constexpr uint32_t SMEM_G128 = 16384 + 2 * 256 * 32;   // 32 KB / stage
    cudaFuncSetAttribute(qkv_kernel,
        cudaFuncAttributeMaxDynamicSharedMemorySize, 2 * SMEM_G128);
    cudaFuncSetAttribute(attn_mma_kernel,
        cudaFuncAttributeMaxDynamicSharedMemorySize, ATTN_SMEM);

    // 1. splits
    split_kernel<<<(NTOT * C / 2 + 255) / 256, 256>>>(x, d_xh, d_xl, NTOT * C / 2);
    split_weights_kernel<<<288, 256>>>(Wv, Wo, Wq, Wk);

    // 2. fused QK + V projections (one launch, 384 CTAs)
    qkv_kernel<<<dim3(128, 3), 256, 2 * SMEM_G128>>>(d_xh, d_xl, bq, bk, bv);

    // 3. attention + fused output projection
    attn_mma_kernel<<<dim3(NTOK / 128, BATCH), 256, ATTN_SMEM>>>(x, bo, out);
}